// round 1
// baseline (speedup 1.0000x reference)
#include <cuda_runtime.h>
#include <math_constants.h>

#define B_  8
#define N_  1024
#define D_  768
#define H_  12
#define HD_ 64
#define M_  (B_*N_)      // 8192
#define C3_ (3*D_)       // 2304

// Scratch (allocation-free rule: __device__ globals)
__device__ float g_q[(size_t)B_*H_*N_*HD_];
__device__ float g_k[(size_t)B_*H_*N_*HD_];
__device__ float g_v[(size_t)B_*H_*N_*HD_];
__device__ float g_ctx[(size_t)M_*D_];

// ---------------------------------------------------------------------------
// Classic 128x128x8 register-blocked SGEMM, 256 threads, 8x8 per thread.
// MODE 0: C = x @ W_qkv + b, scatter into g_q/g_k/g_v as (B,H,N,Hd)
// MODE 1: C = g_ctx @ W_proj + b, plain row-major store to Cout
// ---------------------------------------------------------------------------
template<int NCOLS, int MODE>
__global__ __launch_bounds__(256)
void sgemm_kernel(const float* __restrict__ A,
                  const float* __restrict__ Bmat,
                  const float* __restrict__ bias,
                  float* __restrict__ Cout)
{
    const int K = D_;
    __shared__ float As[8][128];
    __shared__ float Bs[8][128];

    const float* Aptr = (MODE == 1) ? (const float*)g_ctx : A;

    const int t  = threadIdx.x;
    const int m0 = blockIdx.y * 128;
    const int n0 = blockIdx.x * 128;
    const int tx = t & 15;       // 0..15
    const int ty = t >> 4;       // 0..15

    // Load mapping
    const int arow = t >> 1;           // 0..127
    const int acg  = (t & 1) * 4;      // 0 or 4
    const int brow = t >> 5;           // 0..7
    const int bcol = (t & 31) * 4;     // 0..124

    float acc[8][8];
    #pragma unroll
    for (int i = 0; i < 8; i++)
        #pragma unroll
        for (int j = 0; j < 8; j++) acc[i][j] = 0.0f;

    for (int kt = 0; kt < K; kt += 8) {
        float4 av = *(const float4*)(Aptr + (size_t)(m0 + arow) * K + kt + acg);
        float4 bv = *(const float4*)(Bmat + (size_t)(kt + brow) * NCOLS + n0 + bcol);
        __syncthreads();   // previous tile fully consumed
        As[acg + 0][arow] = av.x;
        As[acg + 1][arow] = av.y;
        As[acg + 2][arow] = av.z;
        As[acg + 3][arow] = av.w;
        *(float4*)&Bs[brow][bcol] = bv;
        __syncthreads();

        #pragma unroll
        for (int k = 0; k < 8; k++) {
            float a[8], b[8];
            *(float4*)(a)     = *(const float4*)&As[k][ty * 8];
            *(float4*)(a + 4) = *(const float4*)&As[k][ty * 8 + 4];
            *(float4*)(b)     = *(const float4*)&Bs[k][tx * 8];
            *(float4*)(b + 4) = *(const float4*)&Bs[k][tx * 8 + 4];
            #pragma unroll
            for (int i = 0; i < 8; i++)
                #pragma unroll
                for (int j = 0; j < 8; j++)
                    acc[i][j] += a[i] * b[j];
        }
    }

    #pragma unroll
    for (int i = 0; i < 8; i++) {
        const int m = m0 + ty * 8 + i;
        #pragma unroll
        for (int j = 0; j < 8; j++) {
            const int c = n0 + tx * 8 + j;
            float val = acc[i][j] + bias[c];
            if (MODE == 0) {
                const int bb   = m >> 10;         // m / 1024
                const int n    = m & 1023;
                const int trip = c / D_;
                const int rem  = c - trip * D_;
                const int h    = rem >> 6;        // /64
                const int d    = rem & 63;
                float* dst = (trip == 0) ? g_q : (trip == 1) ? g_k : g_v;
                dst[((((size_t)bb * H_ + h) * N_) + n) * HD_ + d] = val;
            } else {
                Cout[(size_t)m * NCOLS + c] = val;
            }
        }
    }
}

// ---------------------------------------------------------------------------
// Flash attention: grid (N/128, B*H), 128 threads; one query row per thread.
// Q row + O accumulator in registers; K/V tiles (16x64) staged in SMEM and
// consumed via warp-uniform broadcast LDS (conflict-free).
// ---------------------------------------------------------------------------
__global__ __launch_bounds__(128)
void attn_kernel()
{
    const int bh  = blockIdx.y;           // 0..95
    const int b   = bh / H_;
    const int h   = bh - b * H_;
    const int row = blockIdx.x * 128 + threadIdx.x;   // query index in [0,1024)

    const float* __restrict__ Qb = g_q + (size_t)bh * N_ * HD_;
    const float* __restrict__ Kb = g_k + (size_t)bh * N_ * HD_;
    const float* __restrict__ Vb = g_v + (size_t)bh * N_ * HD_;

    float q[64];
    #pragma unroll
    for (int d4 = 0; d4 < 16; d4++)
        *(float4*)&q[4 * d4] = *(const float4*)(Qb + (size_t)row * HD_ + 4 * d4);

    float o[64];
    #pragma unroll
    for (int d = 0; d < 64; d++) o[d] = 0.0f;

    float mmax = -1e30f;
    float l    = 0.0f;
    const float scale = 0.125f;   // 1/sqrt(64)

    __shared__ float Ks[16][64];
    __shared__ float Vs[16][64];

    for (int kt = 0; kt < N_; kt += 16) {
        __syncthreads();
        // stage 16x64 K and V tiles: 256 float4 each; 2 per thread
        #pragma unroll
        for (int r = 0; r < 2; r++) {
            const int fi = threadIdx.x * 2 + r;  // 0..255
            const int kr = fi >> 4;
            const int kc = (fi & 15) * 4;
            *(float4*)&Ks[kr][kc] = *(const float4*)(Kb + (size_t)(kt + kr) * HD_ + kc);
            *(float4*)&Vs[kr][kc] = *(const float4*)(Vb + (size_t)(kt + kr) * HD_ + kc);
        }
        __syncthreads();

        float s[16];
        #pragma unroll
        for (int j = 0; j < 16; j++) {
            float accd = 0.0f;
            #pragma unroll
            for (int d4 = 0; d4 < 16; d4++) {
                float4 kk = *(const float4*)&Ks[j][4 * d4];
                accd += q[4 * d4 + 0] * kk.x;
                accd += q[4 * d4 + 1] * kk.y;
                accd += q[4 * d4 + 2] * kk.z;
                accd += q[4 * d4 + 3] * kk.w;
            }
            s[j] = accd * scale;
        }

        float tmax = s[0];
        #pragma unroll
        for (int j = 1; j < 16; j++) tmax = fmaxf(tmax, s[j]);
        const float mnew = fmaxf(mmax, tmax);
        const float corr = __expf(mmax - mnew);
        l *= corr;
        #pragma unroll
        for (int d = 0; d < 64; d++) o[d] *= corr;

        #pragma unroll
        for (int j = 0; j < 16; j++) {
            const float p = __expf(s[j] - mnew);
            l += p;
            #pragma unroll
            for (int d4 = 0; d4 < 16; d4++) {
                float4 vv = *(const float4*)&Vs[j][4 * d4];
                o[4 * d4 + 0] += p * vv.x;
                o[4 * d4 + 1] += p * vv.y;
                o[4 * d4 + 2] += p * vv.z;
                o[4 * d4 + 3] += p * vv.w;
            }
        }
        mmax = mnew;
    }

    const float inv = 1.0f / l;
    float* outp = g_ctx + ((size_t)(b * N_ + row)) * D_ + h * HD_;
    #pragma unroll
    for (int d4 = 0; d4 < 16; d4++) {
        float4 v;
        v.x = o[4 * d4 + 0] * inv;
        v.y = o[4 * d4 + 1] * inv;
        v.z = o[4 * d4 + 2] * inv;
        v.w = o[4 * d4 + 3] * inv;
        *(float4*)(outp + 4 * d4) = v;
    }
}

// ---------------------------------------------------------------------------
extern "C" void kernel_launch(void* const* d_in, const int* in_sizes, int n_in,
                              void* d_out, int out_size)
{
    const float* x     = (const float*)d_in[0];   // (8,1024,768)
    const float* Wqkv  = (const float*)d_in[1];   // (768,2304)
    const float* bqkv  = (const float*)d_in[2];   // (2304,)
    const float* Wproj = (const float*)d_in[3];   // (768,768)
    const float* bproj = (const float*)d_in[4];   // (768,)
    float* out = (float*)d_out;                   // (8,1024,768)

    // 1) QKV GEMM + bias + scatter to (B,H,N,Hd)
    {
        dim3 grid(C3_ / 128, M_ / 128);  // (18, 64)
        sgemm_kernel<C3_, 0><<<grid, 256>>>(x, Wqkv, bqkv, nullptr);
    }
    // 2) Flash attention into g_ctx (B,N,H*Hd)
    {
        dim3 grid(N_ / 128, B_ * H_);    // (8, 96)
        attn_kernel<<<grid, 128>>>();
    }
    // 3) Output projection
    {
        dim3 grid(D_ / 128, M_ / 128);   // (6, 64)
        sgemm_kernel<D_, 1><<<grid, 256>>>(nullptr, Wproj, bproj, out);
    }
}

// round 3
// speedup vs baseline: 1.5845x; 1.5845x over previous
#include <cuda_runtime.h>
#include <cuda_bf16.h>
#include <cstdint>

#define B_  8
#define N_  1024
#define D_  768
#define H_  12
#define HD_ 64
#define M_  (B_*N_)      // 8192
#define C3_ (3*D_)       // 2304

// ------------------------- scratch (__device__ globals) --------------------
__device__ float g_q[(size_t)B_*H_*N_*HD_];
__device__ float g_k[(size_t)B_*H_*N_*HD_];
__device__ float g_v[(size_t)B_*H_*N_*HD_];
__device__ float g_ctx[(size_t)M_*D_];

__device__ __nv_bfloat16 g_xh[(size_t)M_*D_];
__device__ __nv_bfloat16 g_xl[(size_t)M_*D_];
__device__ __nv_bfloat16 g_ch[(size_t)M_*D_];
__device__ __nv_bfloat16 g_cl[(size_t)M_*D_];
__device__ __nv_bfloat16 g_wh[(size_t)C3_*D_];   // W_qkv^T : [2304][768]
__device__ __nv_bfloat16 g_wl[(size_t)C3_*D_];
__device__ __nv_bfloat16 g_wph[(size_t)D_*D_];   // W_proj^T: [768][768]
__device__ __nv_bfloat16 g_wpl[(size_t)D_*D_];

// ------------------------- helpers -----------------------------------------
__device__ __forceinline__ uint32_t smem_u32(const void* p) {
    uint32_t a;
    asm("{ .reg .u64 t; cvta.to.shared.u64 t, %1; cvt.u32.u64 %0, t; }"
        : "=r"(a) : "l"(p));
    return a;
}
#define SWZ64(o) ((o) ^ (((o) >> 3) & 0x30))

#define CP16(s, g)  asm volatile("cp.async.ca.shared.global [%0], [%1], 16;" :: "r"(s), "l"(g))
#define CPCOMMIT()  asm volatile("cp.async.commit_group;" ::: "memory")
#define CPWAIT(n)   asm volatile("cp.async.wait_group %0;" :: "n"(n) : "memory")

__device__ __forceinline__ void ldsm_x4(uint32_t addr, uint32_t& r0, uint32_t& r1,
                                        uint32_t& r2, uint32_t& r3) {
    asm volatile("ldmatrix.sync.aligned.m8n8.x4.shared.b16 {%0,%1,%2,%3}, [%4];"
                 : "=r"(r0), "=r"(r1), "=r"(r2), "=r"(r3) : "r"(addr));
}
__device__ __forceinline__ void mma16816(float* d, const uint32_t* a, const uint32_t* b) {
    asm volatile(
        "mma.sync.aligned.m16n8k16.row.col.f32.bf16.bf16.f32 "
        "{%0,%1,%2,%3}, {%4,%5,%6,%7}, {%8,%9}, {%0,%1,%2,%3};"
        : "+f"(d[0]), "+f"(d[1]), "+f"(d[2]), "+f"(d[3])
        : "r"(a[0]), "r"(a[1]), "r"(a[2]), "r"(a[3]), "r"(b[0]), "r"(b[1]));
}

// ------------------------- conversion kernels ------------------------------
__global__ void split_x_kernel(const float* __restrict__ in) {
    int i = blockIdx.x * 256 + threadIdx.x;
    if (i < M_ * D_) {
        float v = in[i];
        __nv_bfloat16 h = __float2bfloat16(v);
        g_xh[i] = h;
        g_xl[i] = __float2bfloat16(v - __bfloat162float(h));
    }
}
__global__ void split_ctx_kernel() {
    int i = blockIdx.x * 256 + threadIdx.x;
    if (i < M_ * D_) {
        float v = g_ctx[i];
        __nv_bfloat16 h = __float2bfloat16(v);
        g_ch[i] = h;
        g_cl[i] = __float2bfloat16(v - __bfloat162float(h));
    }
}
// W is [K=768][N] row-major; produce hi/lo transposed [N][768]
template<int WHICH>
__global__ void splitT_kernel(const float* __restrict__ W) {
    constexpr int K = D_;
    constexpr int N = (WHICH == 0) ? C3_ : D_;
    __nv_bfloat16* hi = (WHICH == 0) ? g_wh : g_wph;
    __nv_bfloat16* lo = (WHICH == 0) ? g_wl : g_wpl;
    __shared__ float tile[32][33];
    const int nb = blockIdx.x * 32, kb = blockIdx.y * 32;
    const int tx = threadIdx.x, ty = threadIdx.y;  // 32 x 8
    #pragma unroll
    for (int r = ty; r < 32; r += 8)
        tile[r][tx] = W[(size_t)(kb + r) * N + nb + tx];
    __syncthreads();
    #pragma unroll
    for (int r = ty; r < 32; r += 8) {
        const int n = nb + r, k = kb + tx;
        float v = tile[tx][r];
        __nv_bfloat16 h = __float2bfloat16(v);
        size_t o = (size_t)n * K + k;
        hi[o] = h;
        lo[o] = __float2bfloat16(v - __bfloat162float(h));
    }
}

// ------------------------- HMMA split-bf16 GEMM ------------------------------
// C[m][n] = sum_k A[m][k]*B[n][k] + bias[n], via mma.sync m16n8k16 bf16, 3-pass.
// MODE 0: A = x (hi/lo), B = Wqkv^T, scatter into g_q/g_k/g_v.
// MODE 1: A = ctx (hi/lo), B = Wproj^T, store to Cout.
#define KSTEP_    32
#define NSTEPS_   (D_ / KSTEP_)    // 24
#define TILE_B    8192             // 128 rows * 64 bytes
#define BUF_B     (4 * TILE_B)     // Ah, Al, Bh, Bl
#define SMEM_GEMM (2 * BUF_B)      // 64 KB

template<int MODE>
__global__ __launch_bounds__(256)
void mma_gemm(const float* __restrict__ bias, float* __restrict__ Cout)
{
    extern __shared__ __align__(1024) char smem[];
    const int tid = threadIdx.x, lane = tid & 31, wid = tid >> 5;
    const int m0 = blockIdx.y * 128, n0 = blockIdx.x * 128;
    const int wm = wid & 1;        // 0..1 -> 64 rows each
    const int wn = wid >> 1;       // 0..3 -> 32 cols each

    const __nv_bfloat16* __restrict__ Ah = (MODE == 0) ? g_xh : g_ch;
    const __nv_bfloat16* __restrict__ Al = (MODE == 0) ? g_xl : g_cl;
    const __nv_bfloat16* __restrict__ Bh = (MODE == 0) ? g_wh : g_wph;
    const __nv_bfloat16* __restrict__ Bl = (MODE == 0) ? g_wl : g_wpl;

    // ---- load mapping: 512 16B-chunks per 128x32 tile; 2 per thread --------
    // id = j*256 + tid : row = id/4, chunk c = id%4 (k = c*8)
    const int r0 = tid >> 2,  c0 = tid & 3;          // j=0
    const int r1 = 64 + r0;                          // j=1 (id+256 -> row+64)
    const uint32_t s0 = SWZ64((uint32_t)(r0 * 64 + c0 * 16));
    const uint32_t s1 = SWZ64((uint32_t)(r1 * 64 + c0 * 16));
    const uint32_t sbase = smem_u32(smem);

    // ---- ldmatrix lane offsets (relative to tile base) ----------------------
    // A: rows wm*64 + mi*16 + (lane&15), chunk = kk*2 + (lane>>4)
    const uint32_t aoff = SWZ64((uint32_t)((wm * 64 + (lane & 15)) * 64 + (lane >> 4) * 16));
    // B: rows wn*32 + nb*16 + (lane&7) + ((lane&16)?8:0), chunk = kk*2 + ((lane>>3)&1)
    const uint32_t boff = SWZ64((uint32_t)((wn * 32 + (lane & 7) + ((lane & 16) ? 8 : 0)) * 64
                                           + ((lane >> 3) & 1) * 16));

    float acc[4][4][4];
    #pragma unroll
    for (int i = 0; i < 4; i++)
        #pragma unroll
        for (int j = 0; j < 4; j++)
            #pragma unroll
            for (int e = 0; e < 4; e++) acc[i][j][e] = 0.0f;

    auto load_step = [&](int s, int b) {
        const int kt = s * KSTEP_;
        const uint32_t d = sbase + b * BUF_B;
        const __nv_bfloat16* pa_h = Ah + (size_t)(m0 + r0) * D_ + kt + c0 * 8;
        const __nv_bfloat16* pa_h1 = Ah + (size_t)(m0 + r1) * D_ + kt + c0 * 8;
        const __nv_bfloat16* pa_l = Al + (size_t)(m0 + r0) * D_ + kt + c0 * 8;
        const __nv_bfloat16* pa_l1 = Al + (size_t)(m0 + r1) * D_ + kt + c0 * 8;
        const __nv_bfloat16* pb_h = Bh + (size_t)(n0 + r0) * D_ + kt + c0 * 8;
        const __nv_bfloat16* pb_h1 = Bh + (size_t)(n0 + r1) * D_ + kt + c0 * 8;
        const __nv_bfloat16* pb_l = Bl + (size_t)(n0 + r0) * D_ + kt + c0 * 8;
        const __nv_bfloat16* pb_l1 = Bl + (size_t)(n0 + r1) * D_ + kt + c0 * 8;
        CP16(d + 0 * TILE_B + s0, pa_h);
        CP16(d + 0 * TILE_B + s1, pa_h1);
        CP16(d + 1 * TILE_B + s0, pa_l);
        CP16(d + 1 * TILE_B + s1, pa_l1);
        CP16(d + 2 * TILE_B + s0, pb_h);
        CP16(d + 2 * TILE_B + s1, pb_h1);
        CP16(d + 3 * TILE_B + s0, pb_l);
        CP16(d + 3 * TILE_B + s1, pb_l1);
        CPCOMMIT();
    };

    load_step(0, 0);

    #pragma unroll 1
    for (int s = 0; s < NSTEPS_; s++) {
        const int b = s & 1;
        if (s + 1 < NSTEPS_) { load_step(s + 1, b ^ 1); CPWAIT(1); }
        else                 { CPWAIT(0); }
        __syncthreads();

        const uint32_t tb = sbase + b * BUF_B;
        #pragma unroll
        for (int kk = 0; kk < 2; kk++) {
            const uint32_t kx = kk ? 32u : 0u;
            uint32_t ah[4][4], al[4][4];
            #pragma unroll
            for (int mi = 0; mi < 4; mi++) {
                ldsm_x4((tb + 0 * TILE_B + mi * 1024) + (aoff ^ kx),
                        ah[mi][0], ah[mi][1], ah[mi][2], ah[mi][3]);
                ldsm_x4((tb + 1 * TILE_B + mi * 1024) + (aoff ^ kx),
                        al[mi][0], al[mi][1], al[mi][2], al[mi][3]);
            }
            uint32_t bh[4][2], bl[4][2];
            #pragma unroll
            for (int nb = 0; nb < 2; nb++) {
                ldsm_x4((tb + 2 * TILE_B + nb * 1024) + (boff ^ kx),
                        bh[nb*2][0], bh[nb*2][1], bh[nb*2+1][0], bh[nb*2+1][1]);
                ldsm_x4((tb + 3 * TILE_B + nb * 1024) + (boff ^ kx),
                        bl[nb*2][0], bl[nb*2][1], bl[nb*2+1][0], bl[nb*2+1][1]);
            }
            #pragma unroll
            for (int mi = 0; mi < 4; mi++)
                #pragma unroll
                for (int ni = 0; ni < 4; ni++) {
                    mma16816(acc[mi][ni], ah[mi], bh[ni]);
                    mma16816(acc[mi][ni], ah[mi], bl[ni]);
                    mma16816(acc[mi][ni], al[mi], bh[ni]);
                }
        }
        __syncthreads();
    }

    // ---- epilogue: bias + store/scatter from registers ----------------------
    #pragma unroll
    for (int mi = 0; mi < 4; mi++) {
        #pragma unroll
        for (int ni = 0; ni < 4; ni++) {
            const int cc = n0 + wn * 32 + ni * 8 + (lane & 3) * 2;
            const float b0v = bias[cc], b1v = bias[cc + 1];
            #pragma unroll
            for (int half = 0; half < 2; half++) {
                const int m = m0 + wm * 64 + mi * 16 + (lane >> 2) + half * 8;
                float v0 = acc[mi][ni][half * 2 + 0] + b0v;
                float v1 = acc[mi][ni][half * 2 + 1] + b1v;
                if (MODE == 0) {
                    const int bb = m >> 10, n = m & 1023;
                    const int trip = cc / D_;
                    const int rem = cc - trip * D_;
                    const int h = rem >> 6, d = rem & 63;
                    float* dst = (trip == 0) ? g_q : (trip == 1) ? g_k : g_v;
                    float2* p = (float2*)&dst[((((size_t)bb * H_ + h) * N_) + n) * HD_ + d];
                    *p = make_float2(v0, v1);
                } else {
                    float2* p = (float2*)&Cout[(size_t)m * D_ + cc];
                    *p = make_float2(v0, v1);
                }
            }
        }
    }
}

// ------------------------- flash attention (fp32 SIMT) ----------------------
__global__ __launch_bounds__(128)
void attn_kernel()
{
    const int bh  = blockIdx.y;
    const int b   = bh / H_;
    const int h   = bh - b * H_;
    const int row = blockIdx.x * 128 + threadIdx.x;

    const float* __restrict__ Qb = g_q + (size_t)bh * N_ * HD_;
    const float* __restrict__ Kb = g_k + (size_t)bh * N_ * HD_;
    const float* __restrict__ Vb = g_v + (size_t)bh * N_ * HD_;

    float q[64];
    #pragma unroll
    for (int d4 = 0; d4 < 16; d4++)
        *(float4*)&q[4 * d4] = *(const float4*)(Qb + (size_t)row * HD_ + 4 * d4);

    float o[64];
    #pragma unroll
    for (int d = 0; d < 64; d++) o[d] = 0.0f;

    float mmax = -1e30f;
    float l    = 0.0f;
    const float scale = 0.125f;

    __shared__ float Ks[16][64];
    __shared__ float Vs[16][64];

    for (int kt = 0; kt < N_; kt += 16) {
        __syncthreads();
        #pragma unroll
        for (int r = 0; r < 2; r++) {
            const int fi = threadIdx.x * 2 + r;
            const int kr = fi >> 4;
            const int kc = (fi & 15) * 4;
            *(float4*)&Ks[kr][kc] = *(const float4*)(Kb + (size_t)(kt + kr) * HD_ + kc);
            *(float4*)&Vs[kr][kc] = *(const float4*)(Vb + (size_t)(kt + kr) * HD_ + kc);
        }
        __syncthreads();

        float s[16];
        #pragma unroll
        for (int j = 0; j < 16; j++) {
            float accd = 0.0f;
            #pragma unroll
            for (int d4 = 0; d4 < 16; d4++) {
                float4 kk = *(const float4*)&Ks[j][4 * d4];
                accd += q[4 * d4 + 0] * kk.x;
                accd += q[4 * d4 + 1] * kk.y;
                accd += q[4 * d4 + 2] * kk.z;
                accd += q[4 * d4 + 3] * kk.w;
            }
            s[j] = accd * scale;
        }

        float tmax = s[0];
        #pragma unroll
        for (int j = 1; j < 16; j++) tmax = fmaxf(tmax, s[j]);
        const float mnew = fmaxf(mmax, tmax);
        const float corr = __expf(mmax - mnew);
        l *= corr;
        #pragma unroll
        for (int d = 0; d < 64; d++) o[d] *= corr;

        #pragma unroll
        for (int j = 0; j < 16; j++) {
            const float p = __expf(s[j] - mnew);
            l += p;
            #pragma unroll
            for (int d4 = 0; d4 < 16; d4++) {
                float4 vv = *(const float4*)&Vs[j][4 * d4];
                o[4 * d4 + 0] += p * vv.x;
                o[4 * d4 + 1] += p * vv.y;
                o[4 * d4 + 2] += p * vv.z;
                o[4 * d4 + 3] += p * vv.w;
            }
        }
        mmax = mnew;
    }

    const float inv = 1.0f / l;
    float* outp = g_ctx + ((size_t)(b * N_ + row)) * D_ + h * HD_;
    #pragma unroll
    for (int d4 = 0; d4 < 16; d4++) {
        float4 v;
        v.x = o[4 * d4 + 0] * inv;
        v.y = o[4 * d4 + 1] * inv;
        v.z = o[4 * d4 + 2] * inv;
        v.w = o[4 * d4 + 3] * inv;
        *(float4*)(outp + 4 * d4) = v;
    }
}

// ---------------------------------------------------------------------------
extern "C" void kernel_launch(void* const* d_in, const int* in_sizes, int n_in,
                              void* d_out, int out_size)
{
    const float* x     = (const float*)d_in[0];
    const float* Wqkv  = (const float*)d_in[1];
    const float* bqkv  = (const float*)d_in[2];
    const float* Wproj = (const float*)d_in[3];
    const float* bproj = (const float*)d_in[4];
    float* out = (float*)d_out;

    cudaFuncSetAttribute(mma_gemm<0>, cudaFuncAttributeMaxDynamicSharedMemorySize, SMEM_GEMM);
    cudaFuncSetAttribute(mma_gemm<1>, cudaFuncAttributeMaxDynamicSharedMemorySize, SMEM_GEMM);

    // fp32 -> bf16 hi/lo conversions
    split_x_kernel<<<(M_ * D_ + 255) / 256, 256>>>(x);
    splitT_kernel<0><<<dim3(C3_ / 32, D_ / 32), dim3(32, 8)>>>(Wqkv);
    splitT_kernel<1><<<dim3(D_ / 32, D_ / 32), dim3(32, 8)>>>(Wproj);

    // QKV GEMM (HMMA) + bias + scatter to (B,H,N,Hd)
    mma_gemm<0><<<dim3(C3_ / 128, M_ / 128), 256, SMEM_GEMM>>>(bqkv, nullptr);

    // flash attention into g_ctx
    attn_kernel<<<dim3(N_ / 128, B_ * H_), 128>>>();

    // ctx -> bf16 hi/lo, then output projection (HMMA)
    split_ctx_kernel<<<(M_ * D_ + 255) / 256, 256>>>();
    mma_gemm<1><<<dim3(D_ / 128, M_ / 128), 256, SMEM_GEMM>>>(bproj, out);
}

// round 4
// speedup vs baseline: 3.6725x; 2.3177x over previous
#include <cuda_runtime.h>
#include <cuda_bf16.h>
#include <cstdint>

#define B_  8
#define N_  1024
#define D_  768
#define H_  12
#define HD_ 64
#define M_  (B_*N_)      // 8192
#define C3_ (3*D_)       // 2304
#define SCLOG2E 0.1803368801111204f   // 0.125 * log2(e)

// ------------------------- scratch (__device__ globals) --------------------
__device__ float g_ctx[(size_t)M_*D_];

__device__ __nv_bfloat16 g_qh[(size_t)B_*H_*N_*HD_];
__device__ __nv_bfloat16 g_ql[(size_t)B_*H_*N_*HD_];
__device__ __nv_bfloat16 g_kh[(size_t)B_*H_*N_*HD_];
__device__ __nv_bfloat16 g_kl[(size_t)B_*H_*N_*HD_];
__device__ __nv_bfloat16 g_vh[(size_t)B_*H_*N_*HD_];
__device__ __nv_bfloat16 g_vl[(size_t)B_*H_*N_*HD_];

__device__ __nv_bfloat16 g_xh[(size_t)M_*D_];
__device__ __nv_bfloat16 g_xl[(size_t)M_*D_];
__device__ __nv_bfloat16 g_ch[(size_t)M_*D_];
__device__ __nv_bfloat16 g_cl[(size_t)M_*D_];
__device__ __nv_bfloat16 g_wh[(size_t)C3_*D_];   // W_qkv^T : [2304][768]
__device__ __nv_bfloat16 g_wl[(size_t)C3_*D_];
__device__ __nv_bfloat16 g_wph[(size_t)D_*D_];   // W_proj^T: [768][768]
__device__ __nv_bfloat16 g_wpl[(size_t)D_*D_];

// ------------------------- helpers -----------------------------------------
__device__ __forceinline__ uint32_t smem_u32(const void* p) {
    uint32_t a;
    asm("{ .reg .u64 t; cvta.to.shared.u64 t, %1; cvt.u32.u64 %0, t; }"
        : "=r"(a) : "l"(p));
    return a;
}
#define SWZ64(o)  ((o) ^ (((o) >> 3) & 0x30))
#define SWZ128(o) ((o) ^ (((o) >> 3) & 0x70))

#define CP16(s, g)  asm volatile("cp.async.ca.shared.global [%0], [%1], 16;" :: "r"(s), "l"(g))
#define CPCOMMIT()  asm volatile("cp.async.commit_group;" ::: "memory")
#define CPWAIT(n)   asm volatile("cp.async.wait_group %0;" :: "n"(n) : "memory")

__device__ __forceinline__ void ldsm_x4(uint32_t addr, uint32_t& r0, uint32_t& r1,
                                        uint32_t& r2, uint32_t& r3) {
    asm volatile("ldmatrix.sync.aligned.m8n8.x4.shared.b16 {%0,%1,%2,%3}, [%4];"
                 : "=r"(r0), "=r"(r1), "=r"(r2), "=r"(r3) : "r"(addr));
}
__device__ __forceinline__ void ldsm_x4t(uint32_t addr, uint32_t& r0, uint32_t& r1,
                                         uint32_t& r2, uint32_t& r3) {
    asm volatile("ldmatrix.sync.aligned.m8n8.x4.trans.shared.b16 {%0,%1,%2,%3}, [%4];"
                 : "=r"(r0), "=r"(r1), "=r"(r2), "=r"(r3) : "r"(addr));
}
__device__ __forceinline__ void mma16816(float* d, const uint32_t* a, const uint32_t* b) {
    asm volatile(
        "mma.sync.aligned.m16n8k16.row.col.f32.bf16.bf16.f32 "
        "{%0,%1,%2,%3}, {%4,%5,%6,%7}, {%8,%9}, {%0,%1,%2,%3};"
        : "+f"(d[0]), "+f"(d[1]), "+f"(d[2]), "+f"(d[3])
        : "r"(a[0]), "r"(a[1]), "r"(a[2]), "r"(a[3]), "r"(b[0]), "r"(b[1]));
}
__device__ __forceinline__ float ex2f(float x) {
    float y;
    asm("ex2.approx.f32 %0, %1;" : "=f"(y) : "f"(x));
    return y;
}
// pack: low half = lo, high half = hi
__device__ __forceinline__ uint32_t packbf(float lo, float hi) {
    uint32_t r;
    asm("cvt.rn.bf16x2.f32 %0, %1, %2;" : "=r"(r) : "f"(hi), "f"(lo));
    return r;
}

// ------------------------- conversion kernels ------------------------------
__global__ void split_x_kernel(const float* __restrict__ in) {
    int i = blockIdx.x * 256 + threadIdx.x;
    if (i < M_ * D_) {
        float v = in[i];
        __nv_bfloat16 h = __float2bfloat16(v);
        g_xh[i] = h;
        g_xl[i] = __float2bfloat16(v - __bfloat162float(h));
    }
}
__global__ void split_ctx_kernel() {
    int i = blockIdx.x * 256 + threadIdx.x;
    if (i < M_ * D_) {
        float v = g_ctx[i];
        __nv_bfloat16 h = __float2bfloat16(v);
        g_ch[i] = h;
        g_cl[i] = __float2bfloat16(v - __bfloat162float(h));
    }
}
template<int WHICH>
__global__ void splitT_kernel(const float* __restrict__ W) {
    constexpr int K = D_;
    constexpr int N = (WHICH == 0) ? C3_ : D_;
    __nv_bfloat16* hi = (WHICH == 0) ? g_wh : g_wph;
    __nv_bfloat16* lo = (WHICH == 0) ? g_wl : g_wpl;
    __shared__ float tile[32][33];
    const int nb = blockIdx.x * 32, kb = blockIdx.y * 32;
    const int tx = threadIdx.x, ty = threadIdx.y;
    #pragma unroll
    for (int r = ty; r < 32; r += 8)
        tile[r][tx] = W[(size_t)(kb + r) * N + nb + tx];
    __syncthreads();
    #pragma unroll
    for (int r = ty; r < 32; r += 8) {
        const int n = nb + r, k = kb + tx;
        float v = tile[tx][r];
        __nv_bfloat16 h = __float2bfloat16(v);
        size_t o = (size_t)n * K + k;
        hi[o] = h;
        lo[o] = __float2bfloat16(v - __bfloat162float(h));
    }
}

// ------------------------- HMMA split-bf16 GEMM ------------------------------
#define KSTEP_    32
#define NSTEPS_   (D_ / KSTEP_)    // 24
#define TILE_B    8192             // 128 rows * 64 bytes
#define BUF_B     (4 * TILE_B)
#define SMEM_GEMM (2 * BUF_B)      // 64 KB

template<int MODE>
__global__ __launch_bounds__(256)
void mma_gemm(const float* __restrict__ bias, float* __restrict__ Cout)
{
    extern __shared__ __align__(1024) char smem[];
    const int tid = threadIdx.x, lane = tid & 31, wid = tid >> 5;
    const int m0 = blockIdx.y * 128, n0 = blockIdx.x * 128;
    const int wm = wid & 1;
    const int wn = wid >> 1;

    const __nv_bfloat16* __restrict__ Ah = (MODE == 0) ? g_xh : g_ch;
    const __nv_bfloat16* __restrict__ Al = (MODE == 0) ? g_xl : g_cl;
    const __nv_bfloat16* __restrict__ Bh = (MODE == 0) ? g_wh : g_wph;
    const __nv_bfloat16* __restrict__ Bl = (MODE == 0) ? g_wl : g_wpl;

    const int r0 = tid >> 2,  c0 = tid & 3;
    const int r1 = 64 + r0;
    const uint32_t s0 = SWZ64((uint32_t)(r0 * 64 + c0 * 16));
    const uint32_t s1 = SWZ64((uint32_t)(r1 * 64 + c0 * 16));
    const uint32_t sbase = smem_u32(smem);

    const uint32_t aoff = SWZ64((uint32_t)((wm * 64 + (lane & 15)) * 64 + (lane >> 4) * 16));
    const uint32_t boff = SWZ64((uint32_t)((wn * 32 + (lane & 7) + ((lane & 16) ? 8 : 0)) * 64
                                           + ((lane >> 3) & 1) * 16));

    float acc[4][4][4];
    #pragma unroll
    for (int i = 0; i < 4; i++)
        #pragma unroll
        for (int j = 0; j < 4; j++)
            #pragma unroll
            for (int e = 0; e < 4; e++) acc[i][j][e] = 0.0f;

    auto load_step = [&](int s, int b) {
        const int kt = s * KSTEP_;
        const uint32_t d = sbase + b * BUF_B;
        CP16(d + 0 * TILE_B + s0, Ah + (size_t)(m0 + r0) * D_ + kt + c0 * 8);
        CP16(d + 0 * TILE_B + s1, Ah + (size_t)(m0 + r1) * D_ + kt + c0 * 8);
        CP16(d + 1 * TILE_B + s0, Al + (size_t)(m0 + r0) * D_ + kt + c0 * 8);
        CP16(d + 1 * TILE_B + s1, Al + (size_t)(m0 + r1) * D_ + kt + c0 * 8);
        CP16(d + 2 * TILE_B + s0, Bh + (size_t)(n0 + r0) * D_ + kt + c0 * 8);
        CP16(d + 2 * TILE_B + s1, Bh + (size_t)(n0 + r1) * D_ + kt + c0 * 8);
        CP16(d + 3 * TILE_B + s0, Bl + (size_t)(n0 + r0) * D_ + kt + c0 * 8);
        CP16(d + 3 * TILE_B + s1, Bl + (size_t)(n0 + r1) * D_ + kt + c0 * 8);
        CPCOMMIT();
    };

    load_step(0, 0);

    #pragma unroll 1
    for (int s = 0; s < NSTEPS_; s++) {
        const int b = s & 1;
        if (s + 1 < NSTEPS_) { load_step(s + 1, b ^ 1); CPWAIT(1); }
        else                 { CPWAIT(0); }
        __syncthreads();

        const uint32_t tb = sbase + b * BUF_B;
        #pragma unroll
        for (int kk = 0; kk < 2; kk++) {
            const uint32_t kx = kk ? 32u : 0u;
            uint32_t ah[4][4], al[4][4];
            #pragma unroll
            for (int mi = 0; mi < 4; mi++) {
                ldsm_x4((tb + 0 * TILE_B + mi * 1024) + (aoff ^ kx),
                        ah[mi][0], ah[mi][1], ah[mi][2], ah[mi][3]);
                ldsm_x4((tb + 1 * TILE_B + mi * 1024) + (aoff ^ kx),
                        al[mi][0], al[mi][1], al[mi][2], al[mi][3]);
            }
            uint32_t bh[4][2], bl[4][2];
            #pragma unroll
            for (int nb = 0; nb < 2; nb++) {
                ldsm_x4((tb + 2 * TILE_B + nb * 1024) + (boff ^ kx),
                        bh[nb*2][0], bh[nb*2][1], bh[nb*2+1][0], bh[nb*2+1][1]);
                ldsm_x4((tb + 3 * TILE_B + nb * 1024) + (boff ^ kx),
                        bl[nb*2][0], bl[nb*2][1], bl[nb*2+1][0], bl[nb*2+1][1]);
            }
            #pragma unroll
            for (int mi = 0; mi < 4; mi++)
                #pragma unroll
                for (int ni = 0; ni < 4; ni++) {
                    mma16816(acc[mi][ni], ah[mi], bh[ni]);
                    mma16816(acc[mi][ni], ah[mi], bl[ni]);
                    mma16816(acc[mi][ni], al[mi], bh[ni]);
                }
        }
        __syncthreads();
    }

    // ---- epilogue -----------------------------------------------------------
    #pragma unroll
    for (int mi = 0; mi < 4; mi++) {
        #pragma unroll
        for (int ni = 0; ni < 4; ni++) {
            const int cc = n0 + wn * 32 + ni * 8 + (lane & 3) * 2;
            const float b0v = bias[cc], b1v = bias[cc + 1];
            #pragma unroll
            for (int half = 0; half < 2; half++) {
                const int m = m0 + wm * 64 + mi * 16 + (lane >> 2) + half * 8;
                float v0 = acc[mi][ni][half * 2 + 0] + b0v;
                float v1 = acc[mi][ni][half * 2 + 1] + b1v;
                if (MODE == 0) {
                    const int bb = m >> 10, n = m & 1023;
                    const int trip = cc / D_;
                    const int rem = cc - trip * D_;
                    const int h = rem >> 6, d = rem & 63;
                    const float sc = (trip == 0) ? SCLOG2E : 1.0f;
                    float w0 = v0 * sc, w1 = v1 * sc;
                    __nv_bfloat16 h0 = __float2bfloat16(w0);
                    __nv_bfloat16 h1 = __float2bfloat16(w1);
                    __nv_bfloat16 l0 = __float2bfloat16(w0 - __bfloat162float(h0));
                    __nv_bfloat16 l1 = __float2bfloat16(w1 - __bfloat162float(h1));
                    __nv_bfloat16* dh = (trip == 0) ? g_qh : (trip == 1) ? g_kh : g_vh;
                    __nv_bfloat16* dl = (trip == 0) ? g_ql : (trip == 1) ? g_kl : g_vl;
                    size_t off = ((((size_t)bb * H_ + h) * N_) + n) * HD_ + d;
                    __nv_bfloat162 ph; ph.x = h0; ph.y = h1;
                    __nv_bfloat162 pl; pl.x = l0; pl.y = l1;
                    *(__nv_bfloat162*)(dh + off) = ph;
                    *(__nv_bfloat162*)(dl + off) = pl;
                } else {
                    *(float2*)&Cout[(size_t)m * D_ + cc] = make_float2(v0, v1);
                }
            }
        }
    }
}

// ------------------------- HMMA flash attention ------------------------------
// Grid (N/128, B*H), 256 threads (8 warps x 16 Q rows). Split-bf16 everywhere.
#define ATT_Q_B   32768                 // Qh+Ql: 2 * 128*128B
#define ATT_ST_B  32768                 // Kh,Kl,Vh,Vl: 4 * 64*128B
#define SMEM_ATTN (ATT_Q_B + 2 * ATT_ST_B)   // 96 KB

__global__ __launch_bounds__(256, 1)
void attn_mma()
{
    extern __shared__ __align__(1024) char sm[];
    const uint32_t sb = smem_u32(sm);
    const int tid = threadIdx.x, lane = tid & 31, wid = tid >> 5;
    const int bh = blockIdx.y, q0 = blockIdx.x * 128;
    const size_t bo = (size_t)bh * N_ * HD_;

    const __nv_bfloat16* __restrict__ Qh = g_qh + bo + (size_t)q0 * HD_;
    const __nv_bfloat16* __restrict__ Ql = g_ql + bo + (size_t)q0 * HD_;
    const __nv_bfloat16* __restrict__ Kh = g_kh + bo;
    const __nv_bfloat16* __restrict__ Kl = g_kl + bo;
    const __nv_bfloat16* __restrict__ Vh = g_vh + bo;
    const __nv_bfloat16* __restrict__ Vl = g_vl + bo;

    // ---- Q tiles (hi/lo) -> smem, one group ---------------------------------
    #pragma unroll
    for (int j = 0; j < 8; j++) {
        const int id = j * 256 + tid;
        const int hf = j >> 2;                // 0..3 -> hi, 4..7 -> lo
        const int r  = (id >> 3) & 127;
        const int c  = id & 7;
        const __nv_bfloat16* src = (hf ? Ql : Qh) + (size_t)r * HD_ + c * 8;
        CP16(sb + hf * 16384 + SWZ128((uint32_t)(r * 128 + c * 16)), src);
    }
    CPCOMMIT();

    auto load_kv = [&](int it, int st) {
        const int kt = it * 64;
        #pragma unroll
        for (int j = 0; j < 8; j++) {
            const int id = j * 256 + tid;
            const int t  = j >> 1;            // 0:Kh 1:Kl 2:Vh 3:Vl
            const int r  = (id >> 3) & 63;
            const int c  = id & 7;
            const __nv_bfloat16* src =
                (t == 0 ? Kh : t == 1 ? Kl : t == 2 ? Vh : Vl) + (size_t)(kt + r) * HD_ + c * 8;
            CP16(sb + ATT_Q_B + st * ATT_ST_B + t * 8192 +
                 SWZ128((uint32_t)(r * 128 + c * 16)), src);
        }
        CPCOMMIT();
    };
    load_kv(0, 0);

    CPWAIT(1);             // Q group done (KV0 may still be in flight)
    __syncthreads();

    // ---- Q fragments -> registers ------------------------------------------
    uint32_t qh[4][4], ql[4][4];
    const int arow = wid * 16 + (lane & 15);
    #pragma unroll
    for (int kc = 0; kc < 4; kc++) {
        const uint32_t off = SWZ128((uint32_t)(arow * 128 + (kc * 2 + (lane >> 4)) * 16));
        ldsm_x4(sb + off,         qh[kc][0], qh[kc][1], qh[kc][2], qh[kc][3]);
        ldsm_x4(sb + 16384 + off, ql[kc][0], ql[kc][1], ql[kc][2], ql[kc][3]);
    }

    float o[8][4];
    #pragma unroll
    for (int i = 0; i < 8; i++)
        #pragma unroll
        for (int e = 0; e < 4; e++) o[i][e] = 0.0f;
    float m0r = -1e30f, m1r = -1e30f, l0r = 0.0f, l1r = 0.0f;

    const int krow = (lane & 7) + ((lane >> 4) & 1) * 8;
    const int kchk = (lane >> 3) & 1;
    const int vrow = lane & 15;
    const int vchk = lane >> 4;

    #pragma unroll 1
    for (int it = 0; it < 16; it++) {
        const int st = it & 1;
        if (it + 1 < 16) { load_kv(it + 1, st ^ 1); CPWAIT(1); }
        else             { CPWAIT(0); }
        __syncthreads();
        const uint32_t kb = sb + ATT_Q_B + st * ATT_ST_B;

        // ---- S = Q K^T (split) ----------------------------------------------
        float s[8][4];
        #pragma unroll
        for (int i = 0; i < 8; i++)
            #pragma unroll
            for (int e = 0; e < 4; e++) s[i][e] = 0.0f;

        #pragma unroll
        for (int kc = 0; kc < 4; kc++) {
            #pragma unroll
            for (int p = 0; p < 4; p++) {
                const uint32_t off =
                    SWZ128((uint32_t)((p * 16 + krow) * 128 + (kc * 2 + kchk) * 16));
                uint32_t h0, h1, h2, h3, lo0, lo1, lo2, lo3;
                ldsm_x4(kb + off,        h0, h1, h2, h3);
                ldsm_x4(kb + 8192 + off, lo0, lo1, lo2, lo3);
                uint32_t bh0[2] = {h0, h1}, bh1[2] = {h2, h3};
                uint32_t bl0[2] = {lo0, lo1}, bl1[2] = {lo2, lo3};
                mma16816(s[2*p],     qh[kc], bh0);
                mma16816(s[2*p],     qh[kc], bl0);
                mma16816(s[2*p],     ql[kc], bh0);
                mma16816(s[2*p + 1], qh[kc], bh1);
                mma16816(s[2*p + 1], qh[kc], bl1);
                mma16816(s[2*p + 1], ql[kc], bh1);
            }
        }

        // ---- online softmax ---------------------------------------------------
        float t0 = -1e30f, t1 = -1e30f;
        #pragma unroll
        for (int nt = 0; nt < 8; nt++) {
            t0 = fmaxf(t0, fmaxf(s[nt][0], s[nt][1]));
            t1 = fmaxf(t1, fmaxf(s[nt][2], s[nt][3]));
        }
        t0 = fmaxf(t0, __shfl_xor_sync(0xffffffffu, t0, 1));
        t0 = fmaxf(t0, __shfl_xor_sync(0xffffffffu, t0, 2));
        t1 = fmaxf(t1, __shfl_xor_sync(0xffffffffu, t1, 1));
        t1 = fmaxf(t1, __shfl_xor_sync(0xffffffffu, t1, 2));
        const float mn0 = fmaxf(m0r, t0), mn1 = fmaxf(m1r, t1);
        const float cr0 = ex2f(m0r - mn0), cr1 = ex2f(m1r - mn1);
        m0r = mn0; m1r = mn1;
        l0r *= cr0; l1r *= cr1;
        #pragma unroll
        for (int nt = 0; nt < 8; nt++) {
            o[nt][0] *= cr0; o[nt][1] *= cr0;
            o[nt][2] *= cr1; o[nt][3] *= cr1;
        }
        float ps0 = 0.0f, ps1 = 0.0f;
        #pragma unroll
        for (int nt = 0; nt < 8; nt++) {
            s[nt][0] = ex2f(s[nt][0] - mn0);
            s[nt][1] = ex2f(s[nt][1] - mn0);
            s[nt][2] = ex2f(s[nt][2] - mn1);
            s[nt][3] = ex2f(s[nt][3] - mn1);
            ps0 += s[nt][0] + s[nt][1];
            ps1 += s[nt][2] + s[nt][3];
        }
        l0r += ps0; l1r += ps1;

        // ---- P -> split bf16 A-fragments (register-only) ----------------------
        uint32_t aph[4][4], apl[4][4];
        #pragma unroll
        for (int kc = 0; kc < 4; kc++) {
            #pragma unroll
            for (int g = 0; g < 4; g++) {
                const int nt = 2 * kc + (g >> 1);
                const float x = s[nt][(g & 1) * 2 + 0];
                const float y = s[nt][(g & 1) * 2 + 1];
                const uint32_t hp = packbf(x, y);
                const float hx = __uint_as_float(hp << 16);
                const float hy = __uint_as_float(hp & 0xFFFF0000u);
                aph[kc][g] = hp;
                apl[kc][g] = packbf(x - hx, y - hy);
            }
        }

        // ---- O += P V (split) --------------------------------------------------
        #pragma unroll
        for (int kc = 0; kc < 4; kc++) {
            #pragma unroll
            for (int pr = 0; pr < 4; pr++) {
                const uint32_t off =
                    SWZ128((uint32_t)((kc * 16 + vrow) * 128 + (pr * 2 + vchk) * 16));
                uint32_t h0, h1, h2, h3, lo0, lo1, lo2, lo3;
                ldsm_x4t(kb + 16384 + off, h0, h1, h2, h3);
                ldsm_x4t(kb + 24576 + off, lo0, lo1, lo2, lo3);
                uint32_t vh0[2] = {h0, h1}, vh1[2] = {h2, h3};
                uint32_t vl0[2] = {lo0, lo1}, vl1[2] = {lo2, lo3};
                mma16816(o[2*pr],     aph[kc], vh0);
                mma16816(o[2*pr],     aph[kc], vl0);
                mma16816(o[2*pr],     apl[kc], vh0);
                mma16816(o[2*pr + 1], aph[kc], vh1);
                mma16816(o[2*pr + 1], aph[kc], vl1);
                mma16816(o[2*pr + 1], apl[kc], vh1);
            }
        }
        __syncthreads();
    }

    // ---- finalize: normalize + store to g_ctx --------------------------------
    l0r += __shfl_xor_sync(0xffffffffu, l0r, 1);
    l0r += __shfl_xor_sync(0xffffffffu, l0r, 2);
    l1r += __shfl_xor_sync(0xffffffffu, l1r, 1);
    l1r += __shfl_xor_sync(0xffffffffu, l1r, 2);
    const float inv0 = 1.0f / l0r, inv1 = 1.0f / l1r;

    const int b = bh / H_, h = bh - b * H_;
    const int row0 = q0 + wid * 16 + (lane >> 2);
    float* out0 = g_ctx + ((size_t)(b * N_ + row0)) * D_ + h * HD_ + (lane & 3) * 2;
    float* out1 = out0 + (size_t)8 * D_;
    #pragma unroll
    for (int nt = 0; nt < 8; nt++) {
        *(float2*)(out0 + nt * 8) = make_float2(o[nt][0] * inv0, o[nt][1] * inv0);
        *(float2*)(out1 + nt * 8) = make_float2(o[nt][2] * inv1, o[nt][3] * inv1);
    }
}

// ---------------------------------------------------------------------------
extern "C" void kernel_launch(void* const* d_in, const int* in_sizes, int n_in,
                              void* d_out, int out_size)
{
    const float* x     = (const float*)d_in[0];
    const float* Wqkv  = (const float*)d_in[1];
    const float* bqkv  = (const float*)d_in[2];
    const float* Wproj = (const float*)d_in[3];
    const float* bproj = (const float*)d_in[4];
    float* out = (float*)d_out;

    cudaFuncSetAttribute(mma_gemm<0>, cudaFuncAttributeMaxDynamicSharedMemorySize, SMEM_GEMM);
    cudaFuncSetAttribute(mma_gemm<1>, cudaFuncAttributeMaxDynamicSharedMemorySize, SMEM_GEMM);
    cudaFuncSetAttribute(attn_mma,    cudaFuncAttributeMaxDynamicSharedMemorySize, SMEM_ATTN);

    split_x_kernel<<<(M_ * D_ + 255) / 256, 256>>>(x);
    splitT_kernel<0><<<dim3(C3_ / 32, D_ / 32), dim3(32, 8)>>>(Wqkv);
    splitT_kernel<1><<<dim3(D_ / 32, D_ / 32), dim3(32, 8)>>>(Wproj);

    // QKV GEMM -> bf16 hi/lo Q(K,V) with Q pre-scaled by 0.125*log2(e)
    mma_gemm<0><<<dim3(C3_ / 128, M_ / 128), 256, SMEM_GEMM>>>(bqkv, nullptr);

    // HMMA flash attention -> g_ctx
    attn_mma<<<dim3(N_ / 128, B_ * H_), 256, SMEM_ATTN>>>();

    split_ctx_kernel<<<(M_ * D_ + 255) / 256, 256>>>();
    mma_gemm<1><<<dim3(D_ / 128, M_ / 128), 256, SMEM_GEMM>>>(bproj, out);
}

// round 5
// speedup vs baseline: 3.8255x; 1.0417x over previous
#include <cuda_runtime.h>
#include <cuda_bf16.h>
#include <cstdint>

#define B_  8
#define N_  1024
#define D_  768
#define H_  12
#define HD_ 64
#define M_  (B_*N_)      // 8192
#define C3_ (3*D_)       // 2304
#define SCLOG2E 0.1803368801111204f   // 0.125 * log2(e)

// ------------------------- scratch (__device__ globals) --------------------
__device__ float g_ctx[(size_t)M_*D_];

__device__ __nv_bfloat16 g_qh[(size_t)B_*H_*N_*HD_];
__device__ __nv_bfloat16 g_ql[(size_t)B_*H_*N_*HD_];
__device__ __nv_bfloat16 g_kh[(size_t)B_*H_*N_*HD_];
__device__ __nv_bfloat16 g_kl[(size_t)B_*H_*N_*HD_];
__device__ __nv_bfloat16 g_vh[(size_t)B_*H_*N_*HD_];
__device__ __nv_bfloat16 g_vl[(size_t)B_*H_*N_*HD_];

__device__ __nv_bfloat16 g_xh[(size_t)M_*D_];
__device__ __nv_bfloat16 g_xl[(size_t)M_*D_];
__device__ __nv_bfloat16 g_ch[(size_t)M_*D_];
__device__ __nv_bfloat16 g_cl[(size_t)M_*D_];
__device__ __nv_bfloat16 g_wh[(size_t)C3_*D_];   // W_qkv^T : [2304][768]
__device__ __nv_bfloat16 g_wl[(size_t)C3_*D_];
__device__ __nv_bfloat16 g_wph[(size_t)D_*D_];   // W_proj^T: [768][768]
__device__ __nv_bfloat16 g_wpl[(size_t)D_*D_];

// ------------------------- helpers -----------------------------------------
__device__ __forceinline__ uint32_t smem_u32(const void* p) {
    uint32_t a;
    asm("{ .reg .u64 t; cvta.to.shared.u64 t, %1; cvt.u32.u64 %0, t; }"
        : "=r"(a) : "l"(p));
    return a;
}
#define SWZ64(o)  ((o) ^ (((o) >> 3) & 0x30))
#define SWZ128(o) ((o) ^ (((o) >> 3) & 0x70))

#define CP16(s, g)  asm volatile("cp.async.cg.shared.global [%0], [%1], 16;" :: "r"(s), "l"(g))
#define CPCOMMIT()  asm volatile("cp.async.commit_group;" ::: "memory")
#define CPWAIT(n)   asm volatile("cp.async.wait_group %0;" :: "n"(n) : "memory")

__device__ __forceinline__ void ldsm_x4(uint32_t addr, uint32_t& r0, uint32_t& r1,
                                        uint32_t& r2, uint32_t& r3) {
    asm volatile("ldmatrix.sync.aligned.m8n8.x4.shared.b16 {%0,%1,%2,%3}, [%4];"
                 : "=r"(r0), "=r"(r1), "=r"(r2), "=r"(r3) : "r"(addr));
}
__device__ __forceinline__ void ldsm_x4t(uint32_t addr, uint32_t& r0, uint32_t& r1,
                                         uint32_t& r2, uint32_t& r3) {
    asm volatile("ldmatrix.sync.aligned.m8n8.x4.trans.shared.b16 {%0,%1,%2,%3}, [%4];"
                 : "=r"(r0), "=r"(r1), "=r"(r2), "=r"(r3) : "r"(addr));
}
__device__ __forceinline__ void mma16816(float* d, const uint32_t* a, const uint32_t* b) {
    asm volatile(
        "mma.sync.aligned.m16n8k16.row.col.f32.bf16.bf16.f32 "
        "{%0,%1,%2,%3}, {%4,%5,%6,%7}, {%8,%9}, {%0,%1,%2,%3};"
        : "+f"(d[0]), "+f"(d[1]), "+f"(d[2]), "+f"(d[3])
        : "r"(a[0]), "r"(a[1]), "r"(a[2]), "r"(a[3]), "r"(b[0]), "r"(b[1]));
}
__device__ __forceinline__ float ex2f(float x) {
    float y;
    asm("ex2.approx.f32 %0, %1;" : "=f"(y) : "f"(x));
    return y;
}
__device__ __forceinline__ uint32_t packbf(float lo, float hi) {
    uint32_t r;
    asm("cvt.rn.bf16x2.f32 %0, %1, %2;" : "=r"(r) : "f"(hi), "f"(lo));
    return r;
}

// ------------------------- conversion kernels ------------------------------
__global__ void split_x_kernel(const float* __restrict__ in) {
    int i = blockIdx.x * 256 + threadIdx.x;           // float4 index
    if (i < (M_ * D_) / 4) {
        float4 v = ((const float4*)in)[i];
        __nv_bfloat16 h0 = __float2bfloat16(v.x), h1 = __float2bfloat16(v.y);
        __nv_bfloat16 h2 = __float2bfloat16(v.z), h3 = __float2bfloat16(v.w);
        __nv_bfloat162 H0; H0.x = h0; H0.y = h1;
        __nv_bfloat162 H1; H1.x = h2; H1.y = h3;
        __nv_bfloat162 L0, L1;
        L0.x = __float2bfloat16(v.x - __bfloat162float(h0));
        L0.y = __float2bfloat16(v.y - __bfloat162float(h1));
        L1.x = __float2bfloat16(v.z - __bfloat162float(h2));
        L1.y = __float2bfloat16(v.w - __bfloat162float(h3));
        ((__nv_bfloat162*)g_xh)[i * 2]     = H0;
        ((__nv_bfloat162*)g_xh)[i * 2 + 1] = H1;
        ((__nv_bfloat162*)g_xl)[i * 2]     = L0;
        ((__nv_bfloat162*)g_xl)[i * 2 + 1] = L1;
    }
}
__global__ void split_ctx_kernel() {
    int i = blockIdx.x * 256 + threadIdx.x;
    if (i < (M_ * D_) / 4) {
        float4 v = ((const float4*)g_ctx)[i];
        __nv_bfloat16 h0 = __float2bfloat16(v.x), h1 = __float2bfloat16(v.y);
        __nv_bfloat16 h2 = __float2bfloat16(v.z), h3 = __float2bfloat16(v.w);
        __nv_bfloat162 H0; H0.x = h0; H0.y = h1;
        __nv_bfloat162 H1; H1.x = h2; H1.y = h3;
        __nv_bfloat162 L0, L1;
        L0.x = __float2bfloat16(v.x - __bfloat162float(h0));
        L0.y = __float2bfloat16(v.y - __bfloat162float(h1));
        L1.x = __float2bfloat16(v.z - __bfloat162float(h2));
        L1.y = __float2bfloat16(v.w - __bfloat162float(h3));
        ((__nv_bfloat162*)g_ch)[i * 2]     = H0;
        ((__nv_bfloat162*)g_ch)[i * 2 + 1] = H1;
        ((__nv_bfloat162*)g_cl)[i * 2]     = L0;
        ((__nv_bfloat162*)g_cl)[i * 2 + 1] = L1;
    }
}
template<int WHICH>
__global__ void splitT_kernel(const float* __restrict__ W) {
    constexpr int K = D_;
    constexpr int N = (WHICH == 0) ? C3_ : D_;
    __nv_bfloat16* hi = (WHICH == 0) ? g_wh : g_wph;
    __nv_bfloat16* lo = (WHICH == 0) ? g_wl : g_wpl;
    __shared__ float tile[32][33];
    const int nb = blockIdx.x * 32, kb = blockIdx.y * 32;
    const int tx = threadIdx.x, ty = threadIdx.y;
    #pragma unroll
    for (int r = ty; r < 32; r += 8)
        tile[r][tx] = W[(size_t)(kb + r) * N + nb + tx];
    __syncthreads();
    #pragma unroll
    for (int r = ty; r < 32; r += 8) {
        const int n = nb + r, k = kb + tx;
        float v = tile[tx][r];
        __nv_bfloat16 h = __float2bfloat16(v);
        size_t o = (size_t)n * K + k;
        hi[o] = h;
        lo[o] = __float2bfloat16(v - __bfloat162float(h));
    }
}

// ------------------------- HMMA split-bf16 GEMM (4-stage) --------------------
#define KSTEP_    32
#define NSTEPS_   (D_ / KSTEP_)    // 24
#define TILE_B    8192             // 128 rows * 64 bytes
#define BUF_B     (4 * TILE_B)     // Ah, Al, Bh, Bl  (32 KB / stage)
#define NSTAGE_G  4
#define SMEM_GEMM (NSTAGE_G * BUF_B)   // 128 KB

template<int MODE>
__global__ __launch_bounds__(256)
void mma_gemm(const float* __restrict__ bias, float* __restrict__ Cout)
{
    extern __shared__ __align__(1024) char smem[];
    const int tid = threadIdx.x, lane = tid & 31, wid = tid >> 5;
    const int m0 = blockIdx.y * 128, n0 = blockIdx.x * 128;
    const int wm = wid & 1;
    const int wn = wid >> 1;

    const __nv_bfloat16* __restrict__ Ah = (MODE == 0) ? g_xh : g_ch;
    const __nv_bfloat16* __restrict__ Al = (MODE == 0) ? g_xl : g_cl;
    const __nv_bfloat16* __restrict__ Bh = (MODE == 0) ? g_wh : g_wph;
    const __nv_bfloat16* __restrict__ Bl = (MODE == 0) ? g_wl : g_wpl;

    const int r0 = tid >> 2,  c0 = tid & 3;
    const int r1 = 64 + r0;
    const uint32_t s0 = SWZ64((uint32_t)(r0 * 64 + c0 * 16));
    const uint32_t s1 = SWZ64((uint32_t)(r1 * 64 + c0 * 16));
    const uint32_t sbase = smem_u32(smem);

    const uint32_t aoff = SWZ64((uint32_t)((wm * 64 + (lane & 15)) * 64 + (lane >> 4) * 16));
    const uint32_t boff = SWZ64((uint32_t)((wn * 32 + (lane & 7) + ((lane & 16) ? 8 : 0)) * 64
                                           + ((lane >> 3) & 1) * 16));

    float acc[4][4][4];
    #pragma unroll
    for (int i = 0; i < 4; i++)
        #pragma unroll
        for (int j = 0; j < 4; j++)
            #pragma unroll
            for (int e = 0; e < 4; e++) acc[i][j][e] = 0.0f;

    auto load_step = [&](int s, int st) {
        const int kt = s * KSTEP_;
        const uint32_t d = sbase + st * BUF_B;
        CP16(d + 0 * TILE_B + s0, Ah + (size_t)(m0 + r0) * D_ + kt + c0 * 8);
        CP16(d + 0 * TILE_B + s1, Ah + (size_t)(m0 + r1) * D_ + kt + c0 * 8);
        CP16(d + 1 * TILE_B + s0, Al + (size_t)(m0 + r0) * D_ + kt + c0 * 8);
        CP16(d + 1 * TILE_B + s1, Al + (size_t)(m0 + r1) * D_ + kt + c0 * 8);
        CP16(d + 2 * TILE_B + s0, Bh + (size_t)(n0 + r0) * D_ + kt + c0 * 8);
        CP16(d + 2 * TILE_B + s1, Bh + (size_t)(n0 + r1) * D_ + kt + c0 * 8);
        CP16(d + 3 * TILE_B + s0, Bl + (size_t)(n0 + r0) * D_ + kt + c0 * 8);
        CP16(d + 3 * TILE_B + s1, Bl + (size_t)(n0 + r1) * D_ + kt + c0 * 8);
        CPCOMMIT();
    };

    load_step(0, 0);
    load_step(1, 1);
    load_step(2, 2);
    CPWAIT(2);               // stage 0 ready
    __syncthreads();

    #pragma unroll 1
    for (int s = 0; s < NSTEPS_; s++) {
        // prefetch stage s+3 (overwrites ring slot last read at iter s-1)
        if (s + 3 < NSTEPS_) load_step(s + 3, (s + 3) & 3);

        const uint32_t tb = sbase + (s & 3) * BUF_B;
        #pragma unroll
        for (int kk = 0; kk < 2; kk++) {
            const uint32_t kx = kk ? 32u : 0u;
            uint32_t ah[4][4], al[4][4];
            #pragma unroll
            for (int mi = 0; mi < 4; mi++) {
                ldsm_x4((tb + 0 * TILE_B + mi * 1024) + (aoff ^ kx),
                        ah[mi][0], ah[mi][1], ah[mi][2], ah[mi][3]);
                ldsm_x4((tb + 1 * TILE_B + mi * 1024) + (aoff ^ kx),
                        al[mi][0], al[mi][1], al[mi][2], al[mi][3]);
            }
            uint32_t bh[4][2], bl[4][2];
            #pragma unroll
            for (int nb = 0; nb < 2; nb++) {
                ldsm_x4((tb + 2 * TILE_B + nb * 1024) + (boff ^ kx),
                        bh[nb*2][0], bh[nb*2][1], bh[nb*2+1][0], bh[nb*2+1][1]);
                ldsm_x4((tb + 3 * TILE_B + nb * 1024) + (boff ^ kx),
                        bl[nb*2][0], bl[nb*2][1], bl[nb*2+1][0], bl[nb*2+1][1]);
            }
            #pragma unroll
            for (int mi = 0; mi < 4; mi++)
                #pragma unroll
                for (int ni = 0; ni < 4; ni++) {
                    mma16816(acc[mi][ni], ah[mi], bh[ni]);
                    mma16816(acc[mi][ni], ah[mi], bl[ni]);
                    mma16816(acc[mi][ni], al[mi], bh[ni]);
                }
        }

        // make stage s+1 visible for next iteration
        if (s + 3 < NSTEPS_)      { CPWAIT(2); }
        else if (s + 2 < NSTEPS_) { CPWAIT(1); }
        else if (s + 1 < NSTEPS_) { CPWAIT(0); }
        if (s + 1 < NSTEPS_) __syncthreads();
    }

    // ---- epilogue -----------------------------------------------------------
    #pragma unroll
    for (int mi = 0; mi < 4; mi++) {
        #pragma unroll
        for (int ni = 0; ni < 4; ni++) {
            const int cc = n0 + wn * 32 + ni * 8 + (lane & 3) * 2;
            const float b0v = bias[cc], b1v = bias[cc + 1];
            #pragma unroll
            for (int half = 0; half < 2; half++) {
                const int m = m0 + wm * 64 + mi * 16 + (lane >> 2) + half * 8;
                float v0 = acc[mi][ni][half * 2 + 0] + b0v;
                float v1 = acc[mi][ni][half * 2 + 1] + b1v;
                if (MODE == 0) {
                    const int bb = m >> 10, n = m & 1023;
                    const int trip = cc / D_;
                    const int rem = cc - trip * D_;
                    const int h = rem >> 6, d = rem & 63;
                    const float sc = (trip == 0) ? SCLOG2E : 1.0f;
                    float w0 = v0 * sc, w1 = v1 * sc;
                    __nv_bfloat16 h0 = __float2bfloat16(w0);
                    __nv_bfloat16 h1 = __float2bfloat16(w1);
                    __nv_bfloat16 l0 = __float2bfloat16(w0 - __bfloat162float(h0));
                    __nv_bfloat16 l1 = __float2bfloat16(w1 - __bfloat162float(h1));
                    __nv_bfloat16* dh = (trip == 0) ? g_qh : (trip == 1) ? g_kh : g_vh;
                    __nv_bfloat16* dl = (trip == 0) ? g_ql : (trip == 1) ? g_kl : g_vl;
                    size_t off = ((((size_t)bb * H_ + h) * N_) + n) * HD_ + d;
                    __nv_bfloat162 ph; ph.x = h0; ph.y = h1;
                    __nv_bfloat162 pl; pl.x = l0; pl.y = l1;
                    *(__nv_bfloat162*)(dh + off) = ph;
                    *(__nv_bfloat162*)(dl + off) = pl;
                } else {
                    *(float2*)&Cout[(size_t)m * D_ + cc] = make_float2(v0, v1);
                }
            }
        }
    }
}

// ------------------------- HMMA flash attention (3-stage KV) -----------------
#define ATT_Q_B   32768                 // Qh+Ql: 2 * 128*128B
#define ATT_ST_B  32768                 // Kh,Kl,Vh,Vl: 4 * 64*128B
#define NSTAGE_A  3
#define SMEM_ATTN (ATT_Q_B + NSTAGE_A * ATT_ST_B)   // 128 KB

__global__ __launch_bounds__(256, 1)
void attn_mma()
{
    extern __shared__ __align__(1024) char sm[];
    const uint32_t sb = smem_u32(sm);
    const int tid = threadIdx.x, lane = tid & 31, wid = tid >> 5;
    const int bh = blockIdx.y, q0 = blockIdx.x * 128;
    const size_t bo = (size_t)bh * N_ * HD_;

    const __nv_bfloat16* __restrict__ Qh = g_qh + bo + (size_t)q0 * HD_;
    const __nv_bfloat16* __restrict__ Ql = g_ql + bo + (size_t)q0 * HD_;
    const __nv_bfloat16* __restrict__ Kh = g_kh + bo;
    const __nv_bfloat16* __restrict__ Kl = g_kl + bo;
    const __nv_bfloat16* __restrict__ Vh = g_vh + bo;
    const __nv_bfloat16* __restrict__ Vl = g_vl + bo;

    // ---- Q tiles (hi/lo) -> smem -------------------------------------------
    #pragma unroll
    for (int j = 0; j < 8; j++) {
        const int id = j * 256 + tid;
        const int hf = j >> 2;
        const int r  = (id >> 3) & 127;
        const int c  = id & 7;
        const __nv_bfloat16* src = (hf ? Ql : Qh) + (size_t)r * HD_ + c * 8;
        CP16(sb + hf * 16384 + SWZ128((uint32_t)(r * 128 + c * 16)), src);
    }
    CPCOMMIT();

    auto load_kv = [&](int it, int st) {
        const int kt = it * 64;
        #pragma unroll
        for (int j = 0; j < 8; j++) {
            const int id = j * 256 + tid;
            const int t  = j >> 1;
            const int r  = (id >> 3) & 63;
            const int c  = id & 7;
            const __nv_bfloat16* src =
                (t == 0 ? Kh : t == 1 ? Kl : t == 2 ? Vh : Vl) + (size_t)(kt + r) * HD_ + c * 8;
            CP16(sb + ATT_Q_B + st * ATT_ST_B + t * 8192 +
                 SWZ128((uint32_t)(r * 128 + c * 16)), src);
        }
        CPCOMMIT();
    };
    load_kv(0, 0);
    load_kv(1, 1);

    CPWAIT(1);             // Q + KV0 ready
    __syncthreads();

    // ---- Q fragments -> registers ------------------------------------------
    uint32_t qh[4][4], ql[4][4];
    const int arow = wid * 16 + (lane & 15);
    #pragma unroll
    for (int kc = 0; kc < 4; kc++) {
        const uint32_t off = SWZ128((uint32_t)(arow * 128 + (kc * 2 + (lane >> 4)) * 16));
        ldsm_x4(sb + off,         qh[kc][0], qh[kc][1], qh[kc][2], qh[kc][3]);
        ldsm_x4(sb + 16384 + off, ql[kc][0], ql[kc][1], ql[kc][2], ql[kc][3]);
    }

    float o[8][4];
    #pragma unroll
    for (int i = 0; i < 8; i++)
        #pragma unroll
        for (int e = 0; e < 4; e++) o[i][e] = 0.0f;
    float m0r = -1e30f, m1r = -1e30f, l0r = 0.0f, l1r = 0.0f;

    const int krow = (lane & 7) + ((lane >> 4) & 1) * 8;
    const int kchk = (lane >> 3) & 1;
    const int vrow = lane & 15;
    const int vchk = lane >> 4;

    #pragma unroll 1
    for (int it = 0; it < 16; it++) {
        // prefetch stage it+2 (ring slot last read at it-1)
        if (it + 2 < 16) load_kv(it + 2, (it + 2) % 3);

        const uint32_t kb = sb + ATT_Q_B + (it % 3) * ATT_ST_B;

        // ---- S = Q K^T (split) ----------------------------------------------
        float s[8][4];
        #pragma unroll
        for (int i = 0; i < 8; i++)
            #pragma unroll
            for (int e = 0; e < 4; e++) s[i][e] = 0.0f;

        #pragma unroll
        for (int kc = 0; kc < 4; kc++) {
            #pragma unroll
            for (int p = 0; p < 4; p++) {
                const uint32_t off =
                    SWZ128((uint32_t)((p * 16 + krow) * 128 + (kc * 2 + kchk) * 16));
                uint32_t h0, h1, h2, h3, lo0, lo1, lo2, lo3;
                ldsm_x4(kb + off,        h0, h1, h2, h3);
                ldsm_x4(kb + 8192 + off, lo0, lo1, lo2, lo3);
                uint32_t bh0[2] = {h0, h1}, bh1[2] = {h2, h3};
                uint32_t bl0[2] = {lo0, lo1}, bl1[2] = {lo2, lo3};
                mma16816(s[2*p],     qh[kc], bh0);
                mma16816(s[2*p],     qh[kc], bl0);
                mma16816(s[2*p],     ql[kc], bh0);
                mma16816(s[2*p + 1], qh[kc], bh1);
                mma16816(s[2*p + 1], qh[kc], bl1);
                mma16816(s[2*p + 1], ql[kc], bh1);
            }
        }

        // ---- online softmax ---------------------------------------------------
        float t0 = -1e30f, t1 = -1e30f;
        #pragma unroll
        for (int nt = 0; nt < 8; nt++) {
            t0 = fmaxf(t0, fmaxf(s[nt][0], s[nt][1]));
            t1 = fmaxf(t1, fmaxf(s[nt][2], s[nt][3]));
        }
        t0 = fmaxf(t0, __shfl_xor_sync(0xffffffffu, t0, 1));
        t0 = fmaxf(t0, __shfl_xor_sync(0xffffffffu, t0, 2));
        t1 = fmaxf(t1, __shfl_xor_sync(0xffffffffu, t1, 1));
        t1 = fmaxf(t1, __shfl_xor_sync(0xffffffffu, t1, 2));
        const float mn0 = fmaxf(m0r, t0), mn1 = fmaxf(m1r, t1);
        const float cr0 = ex2f(m0r - mn0), cr1 = ex2f(m1r - mn1);
        m0r = mn0; m1r = mn1;
        l0r *= cr0; l1r *= cr1;
        #pragma unroll
        for (int nt = 0; nt < 8; nt++) {
            o[nt][0] *= cr0; o[nt][1] *= cr0;
            o[nt][2] *= cr1; o[nt][3] *= cr1;
        }
        float ps0 = 0.0f, ps1 = 0.0f;
        #pragma unroll
        for (int nt = 0; nt < 8; nt++) {
            s[nt][0] = ex2f(s[nt][0] - mn0);
            s[nt][1] = ex2f(s[nt][1] - mn0);
            s[nt][2] = ex2f(s[nt][2] - mn1);
            s[nt][3] = ex2f(s[nt][3] - mn1);
            ps0 += s[nt][0] + s[nt][1];
            ps1 += s[nt][2] + s[nt][3];
        }
        l0r += ps0; l1r += ps1;

        // ---- P -> split bf16 A-fragments --------------------------------------
        uint32_t aph[4][4], apl[4][4];
        #pragma unroll
        for (int kc = 0; kc < 4; kc++) {
            #pragma unroll
            for (int g = 0; g < 4; g++) {
                const int nt = 2 * kc + (g >> 1);
                const float x = s[nt][(g & 1) * 2 + 0];
                const float y = s[nt][(g & 1) * 2 + 1];
                const uint32_t hp = packbf(x, y);
                const float hx = __uint_as_float(hp << 16);
                const float hy = __uint_as_float(hp & 0xFFFF0000u);
                aph[kc][g] = hp;
                apl[kc][g] = packbf(x - hx, y - hy);
            }
        }

        // ---- O += P V (split) --------------------------------------------------
        #pragma unroll
        for (int kc = 0; kc < 4; kc++) {
            #pragma unroll
            for (int pr = 0; pr < 4; pr++) {
                const uint32_t off =
                    SWZ128((uint32_t)((kc * 16 + vrow) * 128 + (pr * 2 + vchk) * 16));
                uint32_t h0, h1, h2, h3, lo0, lo1, lo2, lo3;
                ldsm_x4t(kb + 16384 + off, h0, h1, h2, h3);
                ldsm_x4t(kb + 24576 + off, lo0, lo1, lo2, lo3);
                uint32_t vh0[2] = {h0, h1}, vh1[2] = {h2, h3};
                uint32_t vl0[2] = {lo0, lo1}, vl1[2] = {lo2, lo3};
                mma16816(o[2*pr],     aph[kc], vh0);
                mma16816(o[2*pr],     aph[kc], vl0);
                mma16816(o[2*pr],     apl[kc], vh0);
                mma16816(o[2*pr + 1], aph[kc], vh1);
                mma16816(o[2*pr + 1], aph[kc], vl1);
                mma16816(o[2*pr + 1], apl[kc], vh1);
            }
        }

        if (it + 2 < 16)      { CPWAIT(1); }
        else if (it + 1 < 16) { CPWAIT(0); }
        if (it + 1 < 16) __syncthreads();
    }

    // ---- finalize -------------------------------------------------------------
    l0r += __shfl_xor_sync(0xffffffffu, l0r, 1);
    l0r += __shfl_xor_sync(0xffffffffu, l0r, 2);
    l1r += __shfl_xor_sync(0xffffffffu, l1r, 1);
    l1r += __shfl_xor_sync(0xffffffffu, l1r, 2);
    const float inv0 = 1.0f / l0r, inv1 = 1.0f / l1r;

    const int b = bh / H_, h = bh - b * H_;
    const int row0 = q0 + wid * 16 + (lane >> 2);
    float* out0 = g_ctx + ((size_t)(b * N_ + row0)) * D_ + h * HD_ + (lane & 3) * 2;
    float* out1 = out0 + (size_t)8 * D_;
    #pragma unroll
    for (int nt = 0; nt < 8; nt++) {
        *(float2*)(out0 + nt * 8) = make_float2(o[nt][0] * inv0, o[nt][1] * inv0);
        *(float2*)(out1 + nt * 8) = make_float2(o[nt][2] * inv1, o[nt][3] * inv1);
    }
}

// ---------------------------------------------------------------------------
extern "C" void kernel_launch(void* const* d_in, const int* in_sizes, int n_in,
                              void* d_out, int out_size)
{
    const float* x     = (const float*)d_in[0];
    const float* Wqkv  = (const float*)d_in[1];
    const float* bqkv  = (const float*)d_in[2];
    const float* Wproj = (const float*)d_in[3];
    const float* bproj = (const float*)d_in[4];
    float* out = (float*)d_out;

    cudaFuncSetAttribute(mma_gemm<0>, cudaFuncAttributeMaxDynamicSharedMemorySize, SMEM_GEMM);
    cudaFuncSetAttribute(mma_gemm<1>, cudaFuncAttributeMaxDynamicSharedMemorySize, SMEM_GEMM);
    cudaFuncSetAttribute(attn_mma,    cudaFuncAttributeMaxDynamicSharedMemorySize, SMEM_ATTN);

    split_x_kernel<<<(M_ * D_ / 4 + 255) / 256, 256>>>(x);
    splitT_kernel<0><<<dim3(C3_ / 32, D_ / 32), dim3(32, 8)>>>(Wqkv);
    splitT_kernel<1><<<dim3(D_ / 32, D_ / 32), dim3(32, 8)>>>(Wproj);

    mma_gemm<0><<<dim3(C3_ / 128, M_ / 128), 256, SMEM_GEMM>>>(bqkv, nullptr);

    attn_mma<<<dim3(N_ / 128, B_ * H_), 256, SMEM_ATTN>>>();

    split_ctx_kernel<<<(M_ * D_ / 4 + 255) / 256, 256>>>();
    mma_gemm<1><<<dim3(D_ / 128, M_ / 128), 256, SMEM_GEMM>>>(bproj, out);
}

// round 6
// speedup vs baseline: 6.1130x; 1.5980x over previous
#include <cuda_runtime.h>
#include <cuda_bf16.h>
#include <cuda_fp16.h>
#include <cstdint>

#define B_  8
#define N_  1024
#define D_  768
#define H_  12
#define HD_ 64
#define M_  (B_*N_)      // 8192
#define C3_ (3*D_)       // 2304
#define SCLOG2E 0.1803368801111204f   // 0.125 * log2(e)

// ------------------------- scratch (__device__ globals) --------------------
__device__ __half g_cf[(size_t)M_*D_];           // attention output (fp16)

__device__ __nv_bfloat16 g_qh[(size_t)B_*H_*N_*HD_];
__device__ __nv_bfloat16 g_ql[(size_t)B_*H_*N_*HD_];
__device__ __nv_bfloat16 g_kh[(size_t)B_*H_*N_*HD_];
__device__ __nv_bfloat16 g_kl[(size_t)B_*H_*N_*HD_];
__device__ __nv_bfloat16 g_vh[(size_t)B_*H_*N_*HD_];
__device__ __nv_bfloat16 g_vl[(size_t)B_*H_*N_*HD_];

__device__ __half g_xf[(size_t)M_*D_];           // x   (fp16)
__device__ __half g_wf[(size_t)C3_*D_];          // W_qkv^T  [2304][768] fp16
__device__ __half g_wpf[(size_t)D_*D_];          // W_proj^T [768][768]  fp16

// ------------------------- helpers -----------------------------------------
__device__ __forceinline__ uint32_t smem_u32(const void* p) {
    uint32_t a;
    asm("{ .reg .u64 t; cvta.to.shared.u64 t, %1; cvt.u32.u64 %0, t; }"
        : "=r"(a) : "l"(p));
    return a;
}
#define SWZ64(o)  ((o) ^ (((o) >> 3) & 0x30))
#define SWZ128(o) ((o) ^ (((o) >> 3) & 0x70))

#define CP16(s, g)  asm volatile("cp.async.cg.shared.global [%0], [%1], 16;" :: "r"(s), "l"(g))
#define CPCOMMIT()  asm volatile("cp.async.commit_group;" ::: "memory")
#define CPWAIT(n)   asm volatile("cp.async.wait_group %0;" :: "n"(n) : "memory")

__device__ __forceinline__ void ldsm_x4(uint32_t addr, uint32_t& r0, uint32_t& r1,
                                        uint32_t& r2, uint32_t& r3) {
    asm volatile("ldmatrix.sync.aligned.m8n8.x4.shared.b16 {%0,%1,%2,%3}, [%4];"
                 : "=r"(r0), "=r"(r1), "=r"(r2), "=r"(r3) : "r"(addr));
}
__device__ __forceinline__ void ldsm_x4t(uint32_t addr, uint32_t& r0, uint32_t& r1,
                                         uint32_t& r2, uint32_t& r3) {
    asm volatile("ldmatrix.sync.aligned.m8n8.x4.trans.shared.b16 {%0,%1,%2,%3}, [%4];"
                 : "=r"(r0), "=r"(r1), "=r"(r2), "=r"(r3) : "r"(addr));
}
// bf16 mma (attention)
__device__ __forceinline__ void mma16816(float* d, const uint32_t* a, const uint32_t* b) {
    asm volatile(
        "mma.sync.aligned.m16n8k16.row.col.f32.bf16.bf16.f32 "
        "{%0,%1,%2,%3}, {%4,%5,%6,%7}, {%8,%9}, {%0,%1,%2,%3};"
        : "+f"(d[0]), "+f"(d[1]), "+f"(d[2]), "+f"(d[3])
        : "r"(a[0]), "r"(a[1]), "r"(a[2]), "r"(a[3]), "r"(b[0]), "r"(b[1]));
}
// fp16 mma (linear GEMMs)
__device__ __forceinline__ void mma16816h(float* d, const uint32_t* a, const uint32_t* b) {
    asm volatile(
        "mma.sync.aligned.m16n8k16.row.col.f32.f16.f16.f32 "
        "{%0,%1,%2,%3}, {%4,%5,%6,%7}, {%8,%9}, {%0,%1,%2,%3};"
        : "+f"(d[0]), "+f"(d[1]), "+f"(d[2]), "+f"(d[3])
        : "r"(a[0]), "r"(a[1]), "r"(a[2]), "r"(a[3]), "r"(b[0]), "r"(b[1]));
}
__device__ __forceinline__ float ex2f(float x) {
    float y;
    asm("ex2.approx.f32 %0, %1;" : "=f"(y) : "f"(x));
    return y;
}
__device__ __forceinline__ uint32_t packbf(float lo, float hi) {
    uint32_t r;
    asm("cvt.rn.bf16x2.f32 %0, %1, %2;" : "=r"(r) : "f"(hi), "f"(lo));
    return r;
}

// ------------------------- conversion kernels ------------------------------
__global__ void cvt_x_kernel(const float* __restrict__ in) {
    int i = blockIdx.x * 256 + threadIdx.x;           // float4 index
    if (i < (M_ * D_) / 4) {
        float4 v = ((const float4*)in)[i];
        __half2 a = __floats2half2_rn(v.x, v.y);
        __half2 b = __floats2half2_rn(v.z, v.w);
        ((__half2*)g_xf)[i * 2]     = a;
        ((__half2*)g_xf)[i * 2 + 1] = b;
    }
}
// W is [K=768][N] row-major; produce fp16 transposed [N][768]
template<int WHICH>
__global__ void cvtT_kernel(const float* __restrict__ W) {
    constexpr int K = D_;
    constexpr int N = (WHICH == 0) ? C3_ : D_;
    __half* dst = (WHICH == 0) ? g_wf : g_wpf;
    __shared__ float tile[32][33];
    const int nb = blockIdx.x * 32, kb = blockIdx.y * 32;
    const int tx = threadIdx.x, ty = threadIdx.y;
    #pragma unroll
    for (int r = ty; r < 32; r += 8)
        tile[r][tx] = W[(size_t)(kb + r) * N + nb + tx];
    __syncthreads();
    #pragma unroll
    for (int r = ty; r < 32; r += 8) {
        const int n = nb + r, k = kb + tx;
        dst[(size_t)n * K + k] = __float2half_rn(tile[tx][r]);
    }
}

// ------------------------- fp16 single-pass HMMA GEMM -----------------------
// MODE 0: A=g_xf, B=g_wf -> bias + scatter to bf16 hi/lo Q/K/V (Q pre-scaled)
// MODE 1: A=g_cf, B=g_wpf -> bias + fp32 store
#define KSTEP_    32
#define NSTEPS_   (D_ / KSTEP_)    // 24
#define TILE_B    8192             // 128 rows * 64 bytes (fp16 128x32)
#define BUF_B     (2 * TILE_B)     // A, B  (16 KB / stage)
#define NSTAGE_G  4
#define SMEM_GEMM (NSTAGE_G * BUF_B)   // 64 KB

template<int MODE>
__global__ __launch_bounds__(256, 2)
void mma_gemm(const float* __restrict__ bias, float* __restrict__ Cout)
{
    extern __shared__ __align__(1024) char smem[];
    const int tid = threadIdx.x, lane = tid & 31, wid = tid >> 5;
    const int m0 = blockIdx.y * 128, n0 = blockIdx.x * 128;
    const int wm = wid & 1;
    const int wn = wid >> 1;

    const __half* __restrict__ Af = (MODE == 0) ? g_xf : g_cf;
    const __half* __restrict__ Bf = (MODE == 0) ? g_wf : g_wpf;

    const int r0 = tid >> 2,  c0 = tid & 3;
    const int r1 = 64 + r0;
    const uint32_t s0 = SWZ64((uint32_t)(r0 * 64 + c0 * 16));
    const uint32_t s1 = SWZ64((uint32_t)(r1 * 64 + c0 * 16));
    const uint32_t sbase = smem_u32(smem);

    const uint32_t aoff = SWZ64((uint32_t)((wm * 64 + (lane & 15)) * 64 + (lane >> 4) * 16));
    const uint32_t boff = SWZ64((uint32_t)((wn * 32 + (lane & 7) + ((lane & 16) ? 8 : 0)) * 64
                                           + ((lane >> 3) & 1) * 16));

    float acc[4][4][4];
    #pragma unroll
    for (int i = 0; i < 4; i++)
        #pragma unroll
        for (int j = 0; j < 4; j++)
            #pragma unroll
            for (int e = 0; e < 4; e++) acc[i][j][e] = 0.0f;

    auto load_step = [&](int s, int st) {
        const int kt = s * KSTEP_;
        const uint32_t d = sbase + st * BUF_B;
        CP16(d + 0 * TILE_B + s0, Af + (size_t)(m0 + r0) * D_ + kt + c0 * 8);
        CP16(d + 0 * TILE_B + s1, Af + (size_t)(m0 + r1) * D_ + kt + c0 * 8);
        CP16(d + 1 * TILE_B + s0, Bf + (size_t)(n0 + r0) * D_ + kt + c0 * 8);
        CP16(d + 1 * TILE_B + s1, Bf + (size_t)(n0 + r1) * D_ + kt + c0 * 8);
        CPCOMMIT();
    };

    load_step(0, 0);
    load_step(1, 1);
    load_step(2, 2);
    CPWAIT(2);
    __syncthreads();

    #pragma unroll 1
    for (int s = 0; s < NSTEPS_; s++) {
        if (s + 3 < NSTEPS_) load_step(s + 3, (s + 3) & 3);

        const uint32_t tb = sbase + (s & 3) * BUF_B;
        #pragma unroll
        for (int kk = 0; kk < 2; kk++) {
            const uint32_t kx = kk ? 32u : 0u;
            uint32_t ah[4][4];
            #pragma unroll
            for (int mi = 0; mi < 4; mi++)
                ldsm_x4((tb + 0 * TILE_B + mi * 1024) + (aoff ^ kx),
                        ah[mi][0], ah[mi][1], ah[mi][2], ah[mi][3]);
            uint32_t bh[4][2];
            #pragma unroll
            for (int nb = 0; nb < 2; nb++)
                ldsm_x4((tb + 1 * TILE_B + nb * 1024) + (boff ^ kx),
                        bh[nb*2][0], bh[nb*2][1], bh[nb*2+1][0], bh[nb*2+1][1]);
            #pragma unroll
            for (int mi = 0; mi < 4; mi++)
                #pragma unroll
                for (int ni = 0; ni < 4; ni++)
                    mma16816h(acc[mi][ni], ah[mi], bh[ni]);
        }

        if (s + 3 < NSTEPS_)      { CPWAIT(2); }
        else if (s + 2 < NSTEPS_) { CPWAIT(1); }
        else if (s + 1 < NSTEPS_) { CPWAIT(0); }
        if (s + 1 < NSTEPS_) __syncthreads();
    }

    // ---- epilogue -----------------------------------------------------------
    #pragma unroll
    for (int mi = 0; mi < 4; mi++) {
        #pragma unroll
        for (int ni = 0; ni < 4; ni++) {
            const int cc = n0 + wn * 32 + ni * 8 + (lane & 3) * 2;
            const float b0v = bias[cc], b1v = bias[cc + 1];
            #pragma unroll
            for (int half = 0; half < 2; half++) {
                const int m = m0 + wm * 64 + mi * 16 + (lane >> 2) + half * 8;
                float v0 = acc[mi][ni][half * 2 + 0] + b0v;
                float v1 = acc[mi][ni][half * 2 + 1] + b1v;
                if (MODE == 0) {
                    const int bb = m >> 10, n = m & 1023;
                    const int trip = cc / D_;
                    const int rem = cc - trip * D_;
                    const int h = rem >> 6, d = rem & 63;
                    const float sc = (trip == 0) ? SCLOG2E : 1.0f;
                    float w0 = v0 * sc, w1 = v1 * sc;
                    __nv_bfloat16 h0 = __float2bfloat16(w0);
                    __nv_bfloat16 h1 = __float2bfloat16(w1);
                    __nv_bfloat16 l0 = __float2bfloat16(w0 - __bfloat162float(h0));
                    __nv_bfloat16 l1 = __float2bfloat16(w1 - __bfloat162float(h1));
                    __nv_bfloat16* dh = (trip == 0) ? g_qh : (trip == 1) ? g_kh : g_vh;
                    __nv_bfloat16* dl = (trip == 0) ? g_ql : (trip == 1) ? g_kl : g_vl;
                    size_t off = ((((size_t)bb * H_ + h) * N_) + n) * HD_ + d;
                    __nv_bfloat162 ph; ph.x = h0; ph.y = h1;
                    __nv_bfloat162 pl; pl.x = l0; pl.y = l1;
                    *(__nv_bfloat162*)(dh + off) = ph;
                    *(__nv_bfloat162*)(dl + off) = pl;
                } else {
                    *(float2*)&Cout[(size_t)m * D_ + cc] = make_float2(v0, v1);
                }
            }
        }
    }
}

// ------------------------- HMMA flash attention (3-stage KV) -----------------
#define ATT_Q_B   32768                 // Qh+Ql: 2 * 128*128B
#define ATT_ST_B  32768                 // Kh,Kl,Vh,Vl: 4 * 64*128B
#define NSTAGE_A  3
#define SMEM_ATTN (ATT_Q_B + NSTAGE_A * ATT_ST_B)   // 128 KB

__global__ __launch_bounds__(256, 1)
void attn_mma()
{
    extern __shared__ __align__(1024) char sm[];
    const uint32_t sb = smem_u32(sm);
    const int tid = threadIdx.x, lane = tid & 31, wid = tid >> 5;
    const int bh = blockIdx.y, q0 = blockIdx.x * 128;
    const size_t bo = (size_t)bh * N_ * HD_;

    const __nv_bfloat16* __restrict__ Qh = g_qh + bo + (size_t)q0 * HD_;
    const __nv_bfloat16* __restrict__ Ql = g_ql + bo + (size_t)q0 * HD_;
    const __nv_bfloat16* __restrict__ Kh = g_kh + bo;
    const __nv_bfloat16* __restrict__ Kl = g_kl + bo;
    const __nv_bfloat16* __restrict__ Vh = g_vh + bo;
    const __nv_bfloat16* __restrict__ Vl = g_vl + bo;

    #pragma unroll
    for (int j = 0; j < 8; j++) {
        const int id = j * 256 + tid;
        const int hf = j >> 2;
        const int r  = (id >> 3) & 127;
        const int c  = id & 7;
        const __nv_bfloat16* src = (hf ? Ql : Qh) + (size_t)r * HD_ + c * 8;
        CP16(sb + hf * 16384 + SWZ128((uint32_t)(r * 128 + c * 16)), src);
    }
    CPCOMMIT();

    auto load_kv = [&](int it, int st) {
        const int kt = it * 64;
        #pragma unroll
        for (int j = 0; j < 8; j++) {
            const int id = j * 256 + tid;
            const int t  = j >> 1;
            const int r  = (id >> 3) & 63;
            const int c  = id & 7;
            const __nv_bfloat16* src =
                (t == 0 ? Kh : t == 1 ? Kl : t == 2 ? Vh : Vl) + (size_t)(kt + r) * HD_ + c * 8;
            CP16(sb + ATT_Q_B + st * ATT_ST_B + t * 8192 +
                 SWZ128((uint32_t)(r * 128 + c * 16)), src);
        }
        CPCOMMIT();
    };
    load_kv(0, 0);
    load_kv(1, 1);

    CPWAIT(1);
    __syncthreads();

    uint32_t qh[4][4], ql[4][4];
    const int arow = wid * 16 + (lane & 15);
    #pragma unroll
    for (int kc = 0; kc < 4; kc++) {
        const uint32_t off = SWZ128((uint32_t)(arow * 128 + (kc * 2 + (lane >> 4)) * 16));
        ldsm_x4(sb + off,         qh[kc][0], qh[kc][1], qh[kc][2], qh[kc][3]);
        ldsm_x4(sb + 16384 + off, ql[kc][0], ql[kc][1], ql[kc][2], ql[kc][3]);
    }

    float o[8][4];
    #pragma unroll
    for (int i = 0; i < 8; i++)
        #pragma unroll
        for (int e = 0; e < 4; e++) o[i][e] = 0.0f;
    float m0r = -1e30f, m1r = -1e30f, l0r = 0.0f, l1r = 0.0f;

    const int krow = (lane & 7) + ((lane >> 4) & 1) * 8;
    const int kchk = (lane >> 3) & 1;
    const int vrow = lane & 15;
    const int vchk = lane >> 4;

    #pragma unroll 1
    for (int it = 0; it < 16; it++) {
        if (it + 2 < 16) load_kv(it + 2, (it + 2) % 3);

        const uint32_t kb = sb + ATT_Q_B + (it % 3) * ATT_ST_B;

        float s[8][4];
        #pragma unroll
        for (int i = 0; i < 8; i++)
            #pragma unroll
            for (int e = 0; e < 4; e++) s[i][e] = 0.0f;

        #pragma unroll
        for (int kc = 0; kc < 4; kc++) {
            #pragma unroll
            for (int p = 0; p < 4; p++) {
                const uint32_t off =
                    SWZ128((uint32_t)((p * 16 + krow) * 128 + (kc * 2 + kchk) * 16));
                uint32_t h0, h1, h2, h3, lo0, lo1, lo2, lo3;
                ldsm_x4(kb + off,        h0, h1, h2, h3);
                ldsm_x4(kb + 8192 + off, lo0, lo1, lo2, lo3);
                uint32_t bh0[2] = {h0, h1}, bh1[2] = {h2, h3};
                uint32_t bl0[2] = {lo0, lo1}, bl1[2] = {lo2, lo3};
                mma16816(s[2*p],     qh[kc], bh0);
                mma16816(s[2*p],     qh[kc], bl0);
                mma16816(s[2*p],     ql[kc], bh0);
                mma16816(s[2*p + 1], qh[kc], bh1);
                mma16816(s[2*p + 1], qh[kc], bl1);
                mma16816(s[2*p + 1], ql[kc], bh1);
            }
        }

        float t0 = -1e30f, t1 = -1e30f;
        #pragma unroll
        for (int nt = 0; nt < 8; nt++) {
            t0 = fmaxf(t0, fmaxf(s[nt][0], s[nt][1]));
            t1 = fmaxf(t1, fmaxf(s[nt][2], s[nt][3]));
        }
        t0 = fmaxf(t0, __shfl_xor_sync(0xffffffffu, t0, 1));
        t0 = fmaxf(t0, __shfl_xor_sync(0xffffffffu, t0, 2));
        t1 = fmaxf(t1, __shfl_xor_sync(0xffffffffu, t1, 1));
        t1 = fmaxf(t1, __shfl_xor_sync(0xffffffffu, t1, 2));
        const float mn0 = fmaxf(m0r, t0), mn1 = fmaxf(m1r, t1);
        const float cr0 = ex2f(m0r - mn0), cr1 = ex2f(m1r - mn1);
        m0r = mn0; m1r = mn1;
        l0r *= cr0; l1r *= cr1;
        #pragma unroll
        for (int nt = 0; nt < 8; nt++) {
            o[nt][0] *= cr0; o[nt][1] *= cr0;
            o[nt][2] *= cr1; o[nt][3] *= cr1;
        }
        float ps0 = 0.0f, ps1 = 0.0f;
        #pragma unroll
        for (int nt = 0; nt < 8; nt++) {
            s[nt][0] = ex2f(s[nt][0] - mn0);
            s[nt][1] = ex2f(s[nt][1] - mn0);
            s[nt][2] = ex2f(s[nt][2] - mn1);
            s[nt][3] = ex2f(s[nt][3] - mn1);
            ps0 += s[nt][0] + s[nt][1];
            ps1 += s[nt][2] + s[nt][3];
        }
        l0r += ps0; l1r += ps1;

        uint32_t aph[4][4], apl[4][4];
        #pragma unroll
        for (int kc = 0; kc < 4; kc++) {
            #pragma unroll
            for (int g = 0; g < 4; g++) {
                const int nt = 2 * kc + (g >> 1);
                const float x = s[nt][(g & 1) * 2 + 0];
                const float y = s[nt][(g & 1) * 2 + 1];
                const uint32_t hp = packbf(x, y);
                const float hx = __uint_as_float(hp << 16);
                const float hy = __uint_as_float(hp & 0xFFFF0000u);
                aph[kc][g] = hp;
                apl[kc][g] = packbf(x - hx, y - hy);
            }
        }

        #pragma unroll
        for (int kc = 0; kc < 4; kc++) {
            #pragma unroll
            for (int pr = 0; pr < 4; pr++) {
                const uint32_t off =
                    SWZ128((uint32_t)((kc * 16 + vrow) * 128 + (pr * 2 + vchk) * 16));
                uint32_t h0, h1, h2, h3, lo0, lo1, lo2, lo3;
                ldsm_x4t(kb + 16384 + off, h0, h1, h2, h3);
                ldsm_x4t(kb + 24576 + off, lo0, lo1, lo2, lo3);
                uint32_t vh0[2] = {h0, h1}, vh1[2] = {h2, h3};
                uint32_t vl0[2] = {lo0, lo1}, vl1[2] = {lo2, lo3};
                mma16816(o[2*pr],     aph[kc], vh0);
                mma16816(o[2*pr],     aph[kc], vl0);
                mma16816(o[2*pr],     apl[kc], vh0);
                mma16816(o[2*pr + 1], aph[kc], vh1);
                mma16816(o[2*pr + 1], aph[kc], vl1);
                mma16816(o[2*pr + 1], apl[kc], vh1);
            }
        }

        if (it + 2 < 16)      { CPWAIT(1); }
        else if (it + 1 < 16) { CPWAIT(0); }
        if (it + 1 < 16) __syncthreads();
    }

    // ---- finalize: write fp16 ctx directly ------------------------------------
    l0r += __shfl_xor_sync(0xffffffffu, l0r, 1);
    l0r += __shfl_xor_sync(0xffffffffu, l0r, 2);
    l1r += __shfl_xor_sync(0xffffffffu, l1r, 1);
    l1r += __shfl_xor_sync(0xffffffffu, l1r, 2);
    const float inv0 = 1.0f / l0r, inv1 = 1.0f / l1r;

    const int b = bh / H_, h = bh - b * H_;
    const int row0 = q0 + wid * 16 + (lane >> 2);
    __half* out0 = g_cf + ((size_t)(b * N_ + row0)) * D_ + h * HD_ + (lane & 3) * 2;
    __half* out1 = out0 + (size_t)8 * D_;
    #pragma unroll
    for (int nt = 0; nt < 8; nt++) {
        *(__half2*)(out0 + nt * 8) = __floats2half2_rn(o[nt][0] * inv0, o[nt][1] * inv0);
        *(__half2*)(out1 + nt * 8) = __floats2half2_rn(o[nt][2] * inv1, o[nt][3] * inv1);
    }
}

// ---------------------------------------------------------------------------
extern "C" void kernel_launch(void* const* d_in, const int* in_sizes, int n_in,
                              void* d_out, int out_size)
{
    const float* x     = (const float*)d_in[0];
    const float* Wqkv  = (const float*)d_in[1];
    const float* bqkv  = (const float*)d_in[2];
    const float* Wproj = (const float*)d_in[3];
    const float* bproj = (const float*)d_in[4];
    float* out = (float*)d_out;

    cudaFuncSetAttribute(mma_gemm<0>, cudaFuncAttributeMaxDynamicSharedMemorySize, SMEM_GEMM);
    cudaFuncSetAttribute(mma_gemm<1>, cudaFuncAttributeMaxDynamicSharedMemorySize, SMEM_GEMM);
    cudaFuncSetAttribute(attn_mma,    cudaFuncAttributeMaxDynamicSharedMemorySize, SMEM_ATTN);

    cvt_x_kernel<<<(M_ * D_ / 4 + 255) / 256, 256>>>(x);
    cvtT_kernel<0><<<dim3(C3_ / 32, D_ / 32), dim3(32, 8)>>>(Wqkv);
    cvtT_kernel<1><<<dim3(D_ / 32, D_ / 32), dim3(32, 8)>>>(Wproj);

    // QKV GEMM (fp16 single-pass) -> bf16 hi/lo Q/K/V (Q pre-scaled)
    mma_gemm<0><<<dim3(C3_ / 128, M_ / 128), 256, SMEM_GEMM>>>(bqkv, nullptr);

    // split-bf16 HMMA flash attention -> fp16 ctx
    attn_mma<<<dim3(N_ / 128, B_ * H_), 256, SMEM_ATTN>>>();

    // output projection (fp16 single-pass)
    mma_gemm<1><<<dim3(D_ / 128, M_ / 128), 256, SMEM_GEMM>>>(bproj, out);
}

// round 7
// speedup vs baseline: 7.4412x; 1.2173x over previous
#include <cuda_runtime.h>
#include <cuda_bf16.h>
#include <cuda_fp16.h>
#include <cstdint>

#define B_  8
#define N_  1024
#define D_  768
#define H_  12
#define HD_ 64
#define M_  (B_*N_)      // 8192
#define C3_ (3*D_)       // 2304
#define SCLOG2E 0.1803368801111204f   // 0.125 * log2(e)

// ------------------------- scratch (__device__ globals) --------------------
__device__ __half g_cf[(size_t)M_*D_];           // attention output (fp16)

__device__ __nv_bfloat16 g_qh[(size_t)B_*H_*N_*HD_];
__device__ __nv_bfloat16 g_ql[(size_t)B_*H_*N_*HD_];
__device__ __nv_bfloat16 g_kh[(size_t)B_*H_*N_*HD_];
__device__ __nv_bfloat16 g_kl[(size_t)B_*H_*N_*HD_];
__device__ __half        g_vf[(size_t)B_*H_*N_*HD_];   // V single fp16

__device__ __half g_xf[(size_t)M_*D_];           // x   (fp16)
__device__ __half g_wf[(size_t)C3_*D_];          // W_qkv^T  [2304][768] fp16
__device__ __half g_wpf[(size_t)D_*D_];          // W_proj^T [768][768]  fp16

// ------------------------- helpers -----------------------------------------
__device__ __forceinline__ uint32_t smem_u32(const void* p) {
    uint32_t a;
    asm("{ .reg .u64 t; cvta.to.shared.u64 t, %1; cvt.u32.u64 %0, t; }"
        : "=r"(a) : "l"(p));
    return a;
}
#define SWZ64(o)  ((o) ^ (((o) >> 3) & 0x30))
#define SWZ128(o) ((o) ^ (((o) >> 3) & 0x70))

#define CP16(s, g)  asm volatile("cp.async.cg.shared.global [%0], [%1], 16;" :: "r"(s), "l"(g))
#define CPCOMMIT()  asm volatile("cp.async.commit_group;" ::: "memory")
#define CPWAIT(n)   asm volatile("cp.async.wait_group %0;" :: "n"(n) : "memory")

__device__ __forceinline__ void ldsm_x4(uint32_t addr, uint32_t& r0, uint32_t& r1,
                                        uint32_t& r2, uint32_t& r3) {
    asm volatile("ldmatrix.sync.aligned.m8n8.x4.shared.b16 {%0,%1,%2,%3}, [%4];"
                 : "=r"(r0), "=r"(r1), "=r"(r2), "=r"(r3) : "r"(addr));
}
__device__ __forceinline__ void ldsm_x4t(uint32_t addr, uint32_t& r0, uint32_t& r1,
                                         uint32_t& r2, uint32_t& r3) {
    asm volatile("ldmatrix.sync.aligned.m8n8.x4.trans.shared.b16 {%0,%1,%2,%3}, [%4];"
                 : "=r"(r0), "=r"(r1), "=r"(r2), "=r"(r3) : "r"(addr));
}
// bf16 mma (attention S-phase)
__device__ __forceinline__ void mma16816(float* d, const uint32_t* a, const uint32_t* b) {
    asm volatile(
        "mma.sync.aligned.m16n8k16.row.col.f32.bf16.bf16.f32 "
        "{%0,%1,%2,%3}, {%4,%5,%6,%7}, {%8,%9}, {%0,%1,%2,%3};"
        : "+f"(d[0]), "+f"(d[1]), "+f"(d[2]), "+f"(d[3])
        : "r"(a[0]), "r"(a[1]), "r"(a[2]), "r"(a[3]), "r"(b[0]), "r"(b[1]));
}
// fp16 mma (linear GEMMs + PV)
__device__ __forceinline__ void mma16816h(float* d, const uint32_t* a, const uint32_t* b) {
    asm volatile(
        "mma.sync.aligned.m16n8k16.row.col.f32.f16.f16.f32 "
        "{%0,%1,%2,%3}, {%4,%5,%6,%7}, {%8,%9}, {%0,%1,%2,%3};"
        : "+f"(d[0]), "+f"(d[1]), "+f"(d[2]), "+f"(d[3])
        : "r"(a[0]), "r"(a[1]), "r"(a[2]), "r"(a[3]), "r"(b[0]), "r"(b[1]));
}
__device__ __forceinline__ float ex2f(float x) {
    float y;
    asm("ex2.approx.f32 %0, %1;" : "=f"(y) : "f"(x));
    return y;
}
__device__ __forceinline__ uint32_t packhf(float lo, float hi) {
    uint32_t r;
    asm("cvt.rn.f16x2.f32 %0, %1, %2;" : "=r"(r) : "f"(hi), "f"(lo));
    return r;
}

// ------------------------- conversion kernels ------------------------------
__global__ void cvt_x_kernel(const float* __restrict__ in) {
    int i = blockIdx.x * 256 + threadIdx.x;           // float4 index
    if (i < (M_ * D_) / 4) {
        float4 v = ((const float4*)in)[i];
        ((__half2*)g_xf)[i * 2]     = __floats2half2_rn(v.x, v.y);
        ((__half2*)g_xf)[i * 2 + 1] = __floats2half2_rn(v.z, v.w);
    }
}
// W is [K=768][N] row-major; produce fp16 transposed [N][768]
template<int WHICH>
__global__ void cvtT_kernel(const float* __restrict__ W) {
    constexpr int K = D_;
    constexpr int N = (WHICH == 0) ? C3_ : D_;
    __half* dst = (WHICH == 0) ? g_wf : g_wpf;
    __shared__ float tile[32][33];
    const int nb = blockIdx.x * 32, kb = blockIdx.y * 32;
    const int tx = threadIdx.x, ty = threadIdx.y;
    #pragma unroll
    for (int r = ty; r < 32; r += 8)
        tile[r][tx] = W[(size_t)(kb + r) * N + nb + tx];
    __syncthreads();
    #pragma unroll
    for (int r = ty; r < 32; r += 8) {
        const int n = nb + r, k = kb + tx;
        dst[(size_t)n * K + k] = __float2half_rn(tile[tx][r]);
    }
}

// ------------------------- fp16 single-pass HMMA GEMM -----------------------
#define KSTEP_    32
#define NSTEPS_   (D_ / KSTEP_)    // 24
#define TILE_B    8192             // 128 rows * 64 bytes (fp16 128x32)
#define BUF_B     (2 * TILE_B)     // A, B  (16 KB / stage)
#define NSTAGE_G  4
#define SMEM_GEMM (NSTAGE_G * BUF_B)   // 64 KB

template<int MODE>
__global__ __launch_bounds__(256, 2)
void mma_gemm(const float* __restrict__ bias, float* __restrict__ Cout)
{
    extern __shared__ __align__(1024) char smem[];
    const int tid = threadIdx.x, lane = tid & 31, wid = tid >> 5;
    const int m0 = blockIdx.y * 128, n0 = blockIdx.x * 128;
    const int wm = wid & 1;
    const int wn = wid >> 1;

    const __half* __restrict__ Af = (MODE == 0) ? g_xf : g_cf;
    const __half* __restrict__ Bf = (MODE == 0) ? g_wf : g_wpf;

    const int r0 = tid >> 2,  c0 = tid & 3;
    const int r1 = 64 + r0;
    const uint32_t s0 = SWZ64((uint32_t)(r0 * 64 + c0 * 16));
    const uint32_t s1 = SWZ64((uint32_t)(r1 * 64 + c0 * 16));
    const uint32_t sbase = smem_u32(smem);

    const uint32_t aoff = SWZ64((uint32_t)((wm * 64 + (lane & 15)) * 64 + (lane >> 4) * 16));
    const uint32_t boff = SWZ64((uint32_t)((wn * 32 + (lane & 7) + ((lane & 16) ? 8 : 0)) * 64
                                           + ((lane >> 3) & 1) * 16));

    float acc[4][4][4];
    #pragma unroll
    for (int i = 0; i < 4; i++)
        #pragma unroll
        for (int j = 0; j < 4; j++)
            #pragma unroll
            for (int e = 0; e < 4; e++) acc[i][j][e] = 0.0f;

    auto load_step = [&](int s, int st) {
        const int kt = s * KSTEP_;
        const uint32_t d = sbase + st * BUF_B;
        CP16(d + 0 * TILE_B + s0, Af + (size_t)(m0 + r0) * D_ + kt + c0 * 8);
        CP16(d + 0 * TILE_B + s1, Af + (size_t)(m0 + r1) * D_ + kt + c0 * 8);
        CP16(d + 1 * TILE_B + s0, Bf + (size_t)(n0 + r0) * D_ + kt + c0 * 8);
        CP16(d + 1 * TILE_B + s1, Bf + (size_t)(n0 + r1) * D_ + kt + c0 * 8);
        CPCOMMIT();
    };

    load_step(0, 0);
    load_step(1, 1);
    load_step(2, 2);
    CPWAIT(2);
    __syncthreads();

    #pragma unroll 1
    for (int s = 0; s < NSTEPS_; s++) {
        if (s + 3 < NSTEPS_) load_step(s + 3, (s + 3) & 3);

        const uint32_t tb = sbase + (s & 3) * BUF_B;
        #pragma unroll
        for (int kk = 0; kk < 2; kk++) {
            const uint32_t kx = kk ? 32u : 0u;
            uint32_t ah[4][4];
            #pragma unroll
            for (int mi = 0; mi < 4; mi++)
                ldsm_x4((tb + 0 * TILE_B + mi * 1024) + (aoff ^ kx),
                        ah[mi][0], ah[mi][1], ah[mi][2], ah[mi][3]);
            uint32_t bh[4][2];
            #pragma unroll
            for (int nb = 0; nb < 2; nb++)
                ldsm_x4((tb + 1 * TILE_B + nb * 1024) + (boff ^ kx),
                        bh[nb*2][0], bh[nb*2][1], bh[nb*2+1][0], bh[nb*2+1][1]);
            #pragma unroll
            for (int mi = 0; mi < 4; mi++)
                #pragma unroll
                for (int ni = 0; ni < 4; ni++)
                    mma16816h(acc[mi][ni], ah[mi], bh[ni]);
        }

        if (s + 3 < NSTEPS_)      { CPWAIT(2); }
        else if (s + 2 < NSTEPS_) { CPWAIT(1); }
        else if (s + 1 < NSTEPS_) { CPWAIT(0); }
        if (s + 1 < NSTEPS_) __syncthreads();
    }

    // ---- epilogue -----------------------------------------------------------
    #pragma unroll
    for (int mi = 0; mi < 4; mi++) {
        #pragma unroll
        for (int ni = 0; ni < 4; ni++) {
            const int cc = n0 + wn * 32 + ni * 8 + (lane & 3) * 2;
            const float b0v = bias[cc], b1v = bias[cc + 1];
            #pragma unroll
            for (int half = 0; half < 2; half++) {
                const int m = m0 + wm * 64 + mi * 16 + (lane >> 2) + half * 8;
                float v0 = acc[mi][ni][half * 2 + 0] + b0v;
                float v1 = acc[mi][ni][half * 2 + 1] + b1v;
                if (MODE == 0) {
                    const int bb = m >> 10, n = m & 1023;
                    const int trip = cc / D_;
                    const int rem = cc - trip * D_;
                    const int h = rem >> 6, d = rem & 63;
                    size_t off = ((((size_t)bb * H_ + h) * N_) + n) * HD_ + d;
                    if (trip == 2) {
                        *(__half2*)(g_vf + off) = __floats2half2_rn(v0, v1);
                    } else {
                        const float sc = (trip == 0) ? SCLOG2E : 1.0f;
                        float w0 = v0 * sc, w1 = v1 * sc;
                        __nv_bfloat16 h0 = __float2bfloat16(w0);
                        __nv_bfloat16 h1 = __float2bfloat16(w1);
                        __nv_bfloat16 l0 = __float2bfloat16(w0 - __bfloat162float(h0));
                        __nv_bfloat16 l1 = __float2bfloat16(w1 - __bfloat162float(h1));
                        __nv_bfloat16* dh = (trip == 0) ? g_qh : g_kh;
                        __nv_bfloat16* dl = (trip == 0) ? g_ql : g_kl;
                        __nv_bfloat162 ph; ph.x = h0; ph.y = h1;
                        __nv_bfloat162 pl; pl.x = l0; pl.y = l1;
                        *(__nv_bfloat162*)(dh + off) = ph;
                        *(__nv_bfloat162*)(dl + off) = pl;
                    }
                } else {
                    *(float2*)&Cout[(size_t)m * D_ + cc] = make_float2(v0, v1);
                }
            }
        }
    }
}

// ------------------------- HMMA flash attention ------------------------------
// S = split-bf16 3-pass; PV = single-pass fp16. 4-stage KV ring.
#define ATT_Q_B   32768                 // Qh+Ql: 2 * 128*128B
#define ATT_ST_B  24576                 // Kh,Kl (bf16) + Vf (fp16): 3 * 64*128B
#define NSTAGE_A  4
#define SMEM_ATTN (ATT_Q_B + NSTAGE_A * ATT_ST_B)   // 128 KB

__global__ __launch_bounds__(256, 1)
void attn_mma()
{
    extern __shared__ __align__(1024) char sm[];
    const uint32_t sb = smem_u32(sm);
    const int tid = threadIdx.x, lane = tid & 31, wid = tid >> 5;
    const int bh = blockIdx.y, q0 = blockIdx.x * 128;
    const size_t bo = (size_t)bh * N_ * HD_;

    const __nv_bfloat16* __restrict__ Qh = g_qh + bo + (size_t)q0 * HD_;
    const __nv_bfloat16* __restrict__ Ql = g_ql + bo + (size_t)q0 * HD_;
    const __nv_bfloat16* __restrict__ Kh = g_kh + bo;
    const __nv_bfloat16* __restrict__ Kl = g_kl + bo;
    const __half*        __restrict__ Vf = g_vf + bo;

    #pragma unroll
    for (int j = 0; j < 8; j++) {
        const int id = j * 256 + tid;
        const int hf = j >> 2;
        const int r  = (id >> 3) & 127;
        const int c  = id & 7;
        const __nv_bfloat16* src = (hf ? Ql : Qh) + (size_t)r * HD_ + c * 8;
        CP16(sb + hf * 16384 + SWZ128((uint32_t)(r * 128 + c * 16)), src);
    }
    CPCOMMIT();

    auto load_kv = [&](int it, int st) {
        const int kt = it * 64;
        #pragma unroll
        for (int j = 0; j < 6; j++) {
            const int id = (j & 1) * 256 + tid;  // 0..511 within tile
            const int t  = j >> 1;               // 0:Kh 1:Kl 2:Vf
            const int r  = id >> 3;              // 0..63
            const int c  = id & 7;
            const char* src = (t == 0) ? (const char*)(Kh + (size_t)(kt + r) * HD_ + c * 8)
                            : (t == 1) ? (const char*)(Kl + (size_t)(kt + r) * HD_ + c * 8)
                                       : (const char*)(Vf + (size_t)(kt + r) * HD_ + c * 8);
            CP16(sb + ATT_Q_B + st * ATT_ST_B + t * 8192 +
                 SWZ128((uint32_t)(r * 128 + c * 16)), src);
        }
        CPCOMMIT();
    };
    load_kv(0, 0);
    load_kv(1, 1);
    load_kv(2, 2);

    CPWAIT(2);             // Q + KV0 ready
    __syncthreads();

    uint32_t qh[4][4], ql[4][4];
    const int arow = wid * 16 + (lane & 15);
    #pragma unroll
    for (int kc = 0; kc < 4; kc++) {
        const uint32_t off = SWZ128((uint32_t)(arow * 128 + (kc * 2 + (lane >> 4)) * 16));
        ldsm_x4(sb + off,         qh[kc][0], qh[kc][1], qh[kc][2], qh[kc][3]);
        ldsm_x4(sb + 16384 + off, ql[kc][0], ql[kc][1], ql[kc][2], ql[kc][3]);
    }

    float o[8][4];
    #pragma unroll
    for (int i = 0; i < 8; i++)
        #pragma unroll
        for (int e = 0; e < 4; e++) o[i][e] = 0.0f;
    float m0r = -1e30f, m1r = -1e30f, l0r = 0.0f, l1r = 0.0f;

    const int krow = (lane & 7) + ((lane >> 4) & 1) * 8;
    const int kchk = (lane >> 3) & 1;
    const int vrow = lane & 15;
    const int vchk = lane >> 4;

    #pragma unroll 1
    for (int it = 0; it < 16; it++) {
        if (it + 3 < 16) load_kv(it + 3, (it + 3) & 3);

        const uint32_t kb = sb + ATT_Q_B + (it & 3) * ATT_ST_B;

        // ---- S = Q K^T (split bf16, 3-pass) -----------------------------------
        float s[8][4];
        #pragma unroll
        for (int i = 0; i < 8; i++)
            #pragma unroll
            for (int e = 0; e < 4; e++) s[i][e] = 0.0f;

        #pragma unroll
        for (int kc = 0; kc < 4; kc++) {
            #pragma unroll
            for (int p = 0; p < 4; p++) {
                const uint32_t off =
                    SWZ128((uint32_t)((p * 16 + krow) * 128 + (kc * 2 + kchk) * 16));
                uint32_t h0, h1, h2, h3, lo0, lo1, lo2, lo3;
                ldsm_x4(kb + off,        h0, h1, h2, h3);
                ldsm_x4(kb + 8192 + off, lo0, lo1, lo2, lo3);
                uint32_t bh0[2] = {h0, h1}, bh1[2] = {h2, h3};
                uint32_t bl0[2] = {lo0, lo1}, bl1[2] = {lo2, lo3};
                mma16816(s[2*p],     qh[kc], bh0);
                mma16816(s[2*p],     qh[kc], bl0);
                mma16816(s[2*p],     ql[kc], bh0);
                mma16816(s[2*p + 1], qh[kc], bh1);
                mma16816(s[2*p + 1], qh[kc], bl1);
                mma16816(s[2*p + 1], ql[kc], bh1);
            }
        }

        // ---- online softmax ---------------------------------------------------
        float t0 = -1e30f, t1 = -1e30f;
        #pragma unroll
        for (int nt = 0; nt < 8; nt++) {
            t0 = fmaxf(t0, fmaxf(s[nt][0], s[nt][1]));
            t1 = fmaxf(t1, fmaxf(s[nt][2], s[nt][3]));
        }
        t0 = fmaxf(t0, __shfl_xor_sync(0xffffffffu, t0, 1));
        t0 = fmaxf(t0, __shfl_xor_sync(0xffffffffu, t0, 2));
        t1 = fmaxf(t1, __shfl_xor_sync(0xffffffffu, t1, 1));
        t1 = fmaxf(t1, __shfl_xor_sync(0xffffffffu, t1, 2));
        const float mn0 = fmaxf(m0r, t0), mn1 = fmaxf(m1r, t1);
        const float cr0 = ex2f(m0r - mn0), cr1 = ex2f(m1r - mn1);
        m0r = mn0; m1r = mn1;
        l0r *= cr0; l1r *= cr1;
        #pragma unroll
        for (int nt = 0; nt < 8; nt++) {
            o[nt][0] *= cr0; o[nt][1] *= cr0;
            o[nt][2] *= cr1; o[nt][3] *= cr1;
        }
        float ps0 = 0.0f, ps1 = 0.0f;
        #pragma unroll
        for (int nt = 0; nt < 8; nt++) {
            s[nt][0] = ex2f(s[nt][0] - mn0);
            s[nt][1] = ex2f(s[nt][1] - mn0);
            s[nt][2] = ex2f(s[nt][2] - mn1);
            s[nt][3] = ex2f(s[nt][3] - mn1);
            ps0 += s[nt][0] + s[nt][1];
            ps1 += s[nt][2] + s[nt][3];
        }
        l0r += ps0; l1r += ps1;

        // ---- P -> fp16 A-fragments (single) ------------------------------------
        uint32_t aph[4][4];
        #pragma unroll
        for (int kc = 0; kc < 4; kc++) {
            #pragma unroll
            for (int g = 0; g < 4; g++) {
                const int nt = 2 * kc + (g >> 1);
                aph[kc][g] = packhf(s[nt][(g & 1) * 2 + 0], s[nt][(g & 1) * 2 + 1]);
            }
        }

        // ---- O += P V (single-pass fp16) ----------------------------------------
        #pragma unroll
        for (int kc = 0; kc < 4; kc++) {
            #pragma unroll
            for (int pr = 0; pr < 4; pr++) {
                const uint32_t off =
                    SWZ128((uint32_t)((kc * 16 + vrow) * 128 + (pr * 2 + vchk) * 16));
                uint32_t h0, h1, h2, h3;
                ldsm_x4t(kb + 16384 + off, h0, h1, h2, h3);
                uint32_t vh0[2] = {h0, h1}, vh1[2] = {h2, h3};
                mma16816h(o[2*pr],     aph[kc], vh0);
                mma16816h(o[2*pr + 1], aph[kc], vh1);
            }
        }

        if (it + 3 < 16)      { CPWAIT(2); }
        else if (it + 2 < 16) { CPWAIT(1); }
        else if (it + 1 < 16) { CPWAIT(0); }
        if (it + 1 < 16) __syncthreads();
    }

    // ---- finalize: write fp16 ctx directly ------------------------------------
    l0r += __shfl_xor_sync(0xffffffffu, l0r, 1);
    l0r += __shfl_xor_sync(0xffffffffu, l0r, 2);
    l1r += __shfl_xor_sync(0xffffffffu, l1r, 1);
    l1r += __shfl_xor_sync(0xffffffffu, l1r, 2);
    const float inv0 = 1.0f / l0r, inv1 = 1.0f / l1r;

    const int b = bh / H_, h = bh - b * H_;
    const int row0 = q0 + wid * 16 + (lane >> 2);
    __half* out0 = g_cf + ((size_t)(b * N_ + row0)) * D_ + h * HD_ + (lane & 3) * 2;
    __half* out1 = out0 + (size_t)8 * D_;
    #pragma unroll
    for (int nt = 0; nt < 8; nt++) {
        *(__half2*)(out0 + nt * 8) = __floats2half2_rn(o[nt][0] * inv0, o[nt][1] * inv0);
        *(__half2*)(out1 + nt * 8) = __floats2half2_rn(o[nt][2] * inv1, o[nt][3] * inv1);
    }
}

// ---------------------------------------------------------------------------
extern "C" void kernel_launch(void* const* d_in, const int* in_sizes, int n_in,
                              void* d_out, int out_size)
{
    const float* x     = (const float*)d_in[0];
    const float* Wqkv  = (const float*)d_in[1];
    const float* bqkv  = (const float*)d_in[2];
    const float* Wproj = (const float*)d_in[3];
    const float* bproj = (const float*)d_in[4];
    float* out = (float*)d_out;

    cudaFuncSetAttribute(mma_gemm<0>, cudaFuncAttributeMaxDynamicSharedMemorySize, SMEM_GEMM);
    cudaFuncSetAttribute(mma_gemm<1>, cudaFuncAttributeMaxDynamicSharedMemorySize, SMEM_GEMM);
    cudaFuncSetAttribute(attn_mma,    cudaFuncAttributeMaxDynamicSharedMemorySize, SMEM_ATTN);

    cvt_x_kernel<<<(M_ * D_ / 4 + 255) / 256, 256>>>(x);
    cvtT_kernel<0><<<dim3(C3_ / 32, D_ / 32), dim3(32, 8)>>>(Wqkv);
    cvtT_kernel<1><<<dim3(D_ / 32, D_ / 32), dim3(32, 8)>>>(Wproj);

    // QKV GEMM (fp16) -> bf16 hi/lo Q,K (Q pre-scaled) + fp16 V
    mma_gemm<0><<<dim3(C3_ / 128, M_ / 128), 256, SMEM_GEMM>>>(bqkv, nullptr);

    // flash attention: split-bf16 S, fp16 PV -> fp16 ctx
    attn_mma<<<dim3(N_ / 128, B_ * H_), 256, SMEM_ATTN>>>();

    // output projection (fp16)
    mma_gemm<1><<<dim3(D_ / 128, M_ / 128), 256, SMEM_GEMM>>>(bproj, out);
}

// round 8
// speedup vs baseline: 8.3555x; 1.1229x over previous
#include <cuda_runtime.h>
#include <cuda_bf16.h>
#include <cuda_fp16.h>
#include <cstdint>

#define B_  8
#define N_  1024
#define D_  768
#define H_  12
#define HD_ 64
#define M_  (B_*N_)      // 8192
#define C3_ (3*D_)       // 2304
#define SCLOG2E 0.1803368801111204f   // 0.125 * log2(e)

// ------------------------- scratch (__device__ globals) --------------------
__device__ __half g_cf[(size_t)M_*D_];           // attention output (fp16)

__device__ __half g_qh[(size_t)B_*H_*N_*HD_];    // Q fp16 hi (pre-scaled)
__device__ __half g_ql[(size_t)B_*H_*N_*HD_];    // Q fp16 residual
__device__ __half g_kf[(size_t)B_*H_*N_*HD_];    // K single fp16
__device__ __half g_vf[(size_t)B_*H_*N_*HD_];    // V single fp16

__device__ __half g_xf[(size_t)M_*D_];           // x   (fp16)
__device__ __half g_wf[(size_t)C3_*D_];          // W_qkv^T  [2304][768] fp16
__device__ __half g_wpf[(size_t)D_*D_];          // W_proj^T [768][768]  fp16

// ------------------------- helpers -----------------------------------------
__device__ __forceinline__ uint32_t smem_u32(const void* p) {
    uint32_t a;
    asm("{ .reg .u64 t; cvta.to.shared.u64 t, %1; cvt.u32.u64 %0, t; }"
        : "=r"(a) : "l"(p));
    return a;
}
#define SWZ64(o)  ((o) ^ (((o) >> 3) & 0x30))
#define SWZ128(o) ((o) ^ (((o) >> 3) & 0x70))

#define CP16(s, g)  asm volatile("cp.async.cg.shared.global [%0], [%1], 16;" :: "r"(s), "l"(g))
#define CPCOMMIT()  asm volatile("cp.async.commit_group;" ::: "memory")
#define CPWAIT(n)   asm volatile("cp.async.wait_group %0;" :: "n"(n) : "memory")

__device__ __forceinline__ void ldsm_x4(uint32_t addr, uint32_t& r0, uint32_t& r1,
                                        uint32_t& r2, uint32_t& r3) {
    asm volatile("ldmatrix.sync.aligned.m8n8.x4.shared.b16 {%0,%1,%2,%3}, [%4];"
                 : "=r"(r0), "=r"(r1), "=r"(r2), "=r"(r3) : "r"(addr));
}
__device__ __forceinline__ void ldsm_x4t(uint32_t addr, uint32_t& r0, uint32_t& r1,
                                         uint32_t& r2, uint32_t& r3) {
    asm volatile("ldmatrix.sync.aligned.m8n8.x4.trans.shared.b16 {%0,%1,%2,%3}, [%4];"
                 : "=r"(r0), "=r"(r1), "=r"(r2), "=r"(r3) : "r"(addr));
}
// fp16 mma (everything)
__device__ __forceinline__ void mma16816h(float* d, const uint32_t* a, const uint32_t* b) {
    asm volatile(
        "mma.sync.aligned.m16n8k16.row.col.f32.f16.f16.f32 "
        "{%0,%1,%2,%3}, {%4,%5,%6,%7}, {%8,%9}, {%0,%1,%2,%3};"
        : "+f"(d[0]), "+f"(d[1]), "+f"(d[2]), "+f"(d[3])
        : "r"(a[0]), "r"(a[1]), "r"(a[2]), "r"(a[3]), "r"(b[0]), "r"(b[1]));
}
__device__ __forceinline__ float ex2f(float x) {
    float y;
    asm("ex2.approx.f32 %0, %1;" : "=f"(y) : "f"(x));
    return y;
}
__device__ __forceinline__ uint32_t packhf(float lo, float hi) {
    uint32_t r;
    asm("cvt.rn.f16x2.f32 %0, %1, %2;" : "=r"(r) : "f"(hi), "f"(lo));
    return r;
}

// ------------------------- conversion kernels ------------------------------
__global__ void cvt_x_kernel(const float* __restrict__ in) {
    int i = blockIdx.x * 256 + threadIdx.x;           // float4 index
    if (i < (M_ * D_) / 4) {
        float4 v = ((const float4*)in)[i];
        ((__half2*)g_xf)[i * 2]     = __floats2half2_rn(v.x, v.y);
        ((__half2*)g_xf)[i * 2 + 1] = __floats2half2_rn(v.z, v.w);
    }
}
// W is [K=768][N] row-major; produce fp16 transposed [N][768]
template<int WHICH>
__global__ void cvtT_kernel(const float* __restrict__ W) {
    constexpr int K = D_;
    constexpr int N = (WHICH == 0) ? C3_ : D_;
    __half* dst = (WHICH == 0) ? g_wf : g_wpf;
    __shared__ float tile[32][33];
    const int nb = blockIdx.x * 32, kb = blockIdx.y * 32;
    const int tx = threadIdx.x, ty = threadIdx.y;
    #pragma unroll
    for (int r = ty; r < 32; r += 8)
        tile[r][tx] = W[(size_t)(kb + r) * N + nb + tx];
    __syncthreads();
    #pragma unroll
    for (int r = ty; r < 32; r += 8) {
        const int n = nb + r, k = kb + tx;
        dst[(size_t)n * K + k] = __float2half_rn(tile[tx][r]);
    }
}

// ------------------------- fp16 single-pass HMMA GEMM -----------------------
#define KSTEP_    32
#define NSTEPS_   (D_ / KSTEP_)    // 24
#define TILE_B    8192             // 128 rows * 64 bytes (fp16 128x32)
#define BUF_B     (2 * TILE_B)     // A, B  (16 KB / stage)
#define NSTAGE_G  4
#define SMEM_GEMM (NSTAGE_G * BUF_B)   // 64 KB

template<int MODE>
__global__ __launch_bounds__(256, 2)
void mma_gemm(const float* __restrict__ bias, float* __restrict__ Cout)
{
    extern __shared__ __align__(1024) char smem[];
    const int tid = threadIdx.x, lane = tid & 31, wid = tid >> 5;
    const int m0 = blockIdx.y * 128, n0 = blockIdx.x * 128;
    const int wm = wid & 1;
    const int wn = wid >> 1;

    const __half* __restrict__ Af = (MODE == 0) ? g_xf : g_cf;
    const __half* __restrict__ Bf = (MODE == 0) ? g_wf : g_wpf;

    const int r0 = tid >> 2,  c0 = tid & 3;
    const int r1 = 64 + r0;
    const uint32_t s0 = SWZ64((uint32_t)(r0 * 64 + c0 * 16));
    const uint32_t s1 = SWZ64((uint32_t)(r1 * 64 + c0 * 16));
    const uint32_t sbase = smem_u32(smem);

    const uint32_t aoff = SWZ64((uint32_t)((wm * 64 + (lane & 15)) * 64 + (lane >> 4) * 16));
    const uint32_t boff = SWZ64((uint32_t)((wn * 32 + (lane & 7) + ((lane & 16) ? 8 : 0)) * 64
                                           + ((lane >> 3) & 1) * 16));

    float acc[4][4][4];
    #pragma unroll
    for (int i = 0; i < 4; i++)
        #pragma unroll
        for (int j = 0; j < 4; j++)
            #pragma unroll
            for (int e = 0; e < 4; e++) acc[i][j][e] = 0.0f;

    auto load_step = [&](int s, int st) {
        const int kt = s * KSTEP_;
        const uint32_t d = sbase + st * BUF_B;
        CP16(d + 0 * TILE_B + s0, Af + (size_t)(m0 + r0) * D_ + kt + c0 * 8);
        CP16(d + 0 * TILE_B + s1, Af + (size_t)(m0 + r1) * D_ + kt + c0 * 8);
        CP16(d + 1 * TILE_B + s0, Bf + (size_t)(n0 + r0) * D_ + kt + c0 * 8);
        CP16(d + 1 * TILE_B + s1, Bf + (size_t)(n0 + r1) * D_ + kt + c0 * 8);
        CPCOMMIT();
    };

    load_step(0, 0);
    load_step(1, 1);
    load_step(2, 2);
    CPWAIT(2);
    __syncthreads();

    #pragma unroll 1
    for (int s = 0; s < NSTEPS_; s++) {
        if (s + 3 < NSTEPS_) load_step(s + 3, (s + 3) & 3);

        const uint32_t tb = sbase + (s & 3) * BUF_B;
        #pragma unroll
        for (int kk = 0; kk < 2; kk++) {
            const uint32_t kx = kk ? 32u : 0u;
            uint32_t ah[4][4];
            #pragma unroll
            for (int mi = 0; mi < 4; mi++)
                ldsm_x4((tb + 0 * TILE_B + mi * 1024) + (aoff ^ kx),
                        ah[mi][0], ah[mi][1], ah[mi][2], ah[mi][3]);
            uint32_t bh[4][2];
            #pragma unroll
            for (int nb = 0; nb < 2; nb++)
                ldsm_x4((tb + 1 * TILE_B + nb * 1024) + (boff ^ kx),
                        bh[nb*2][0], bh[nb*2][1], bh[nb*2+1][0], bh[nb*2+1][1]);
            #pragma unroll
            for (int mi = 0; mi < 4; mi++)
                #pragma unroll
                for (int ni = 0; ni < 4; ni++)
                    mma16816h(acc[mi][ni], ah[mi], bh[ni]);
        }

        if (s + 3 < NSTEPS_)      { CPWAIT(2); }
        else if (s + 2 < NSTEPS_) { CPWAIT(1); }
        else if (s + 1 < NSTEPS_) { CPWAIT(0); }
        if (s + 1 < NSTEPS_) __syncthreads();
    }

    // ---- epilogue -----------------------------------------------------------
    #pragma unroll
    for (int mi = 0; mi < 4; mi++) {
        #pragma unroll
        for (int ni = 0; ni < 4; ni++) {
            const int cc = n0 + wn * 32 + ni * 8 + (lane & 3) * 2;
            const float b0v = bias[cc], b1v = bias[cc + 1];
            #pragma unroll
            for (int half = 0; half < 2; half++) {
                const int m = m0 + wm * 64 + mi * 16 + (lane >> 2) + half * 8;
                float v0 = acc[mi][ni][half * 2 + 0] + b0v;
                float v1 = acc[mi][ni][half * 2 + 1] + b1v;
                if (MODE == 0) {
                    const int bb = m >> 10, n = m & 1023;
                    const int trip = cc / D_;
                    const int rem = cc - trip * D_;
                    const int h = rem >> 6, d = rem & 63;
                    size_t off = ((((size_t)bb * H_ + h) * N_) + n) * HD_ + d;
                    if (trip == 0) {
                        // Q: pre-scaled, split fp16 hi + residual
                        float w0 = v0 * SCLOG2E, w1 = v1 * SCLOG2E;
                        __half h0 = __float2half_rn(w0);
                        __half h1 = __float2half_rn(w1);
                        __half l0 = __float2half_rn(w0 - __half2float(h0));
                        __half l1 = __float2half_rn(w1 - __half2float(h1));
                        __half2 ph; ph.x = h0; ph.y = h1;
                        __half2 pl; pl.x = l0; pl.y = l1;
                        *(__half2*)(g_qh + off) = ph;
                        *(__half2*)(g_ql + off) = pl;
                    } else if (trip == 1) {
                        *(__half2*)(g_kf + off) = __floats2half2_rn(v0, v1);
                    } else {
                        *(__half2*)(g_vf + off) = __floats2half2_rn(v0, v1);
                    }
                } else {
                    *(float2*)&Cout[(size_t)m * D_ + cc] = make_float2(v0, v1);
                }
            }
        }
    }
}

// ------------------------- HMMA flash attention ------------------------------
// S = Qh*Kf + Ql*Kf (2-pass fp16, Q exact to 2^-22); PV = single-pass fp16.
#define ATT_Q_B   32768                 // Qh+Ql: 2 * 128*128B
#define ATT_ST_B  16384                 // Kf + Vf: 2 * 64*128B
#define NSTAGE_A  4
#define SMEM_ATTN (ATT_Q_B + NSTAGE_A * ATT_ST_B)   // 96 KB

__global__ __launch_bounds__(256, 1)
void attn_mma()
{
    extern __shared__ __align__(1024) char sm[];
    const uint32_t sb = smem_u32(sm);
    const int tid = threadIdx.x, lane = tid & 31, wid = tid >> 5;
    const int bh = blockIdx.y, q0 = blockIdx.x * 128;
    const size_t bo = (size_t)bh * N_ * HD_;

    const __half* __restrict__ Qh = g_qh + bo + (size_t)q0 * HD_;
    const __half* __restrict__ Ql = g_ql + bo + (size_t)q0 * HD_;
    const __half* __restrict__ Kf = g_kf + bo;
    const __half* __restrict__ Vf = g_vf + bo;

    #pragma unroll
    for (int j = 0; j < 8; j++) {
        const int id = j * 256 + tid;
        const int hf = j >> 2;
        const int r  = (id >> 3) & 127;
        const int c  = id & 7;
        const __half* src = (hf ? Ql : Qh) + (size_t)r * HD_ + c * 8;
        CP16(sb + hf * 16384 + SWZ128((uint32_t)(r * 128 + c * 16)), src);
    }
    CPCOMMIT();

    auto load_kv = [&](int it, int st) {
        const int kt = it * 64;
        #pragma unroll
        for (int j = 0; j < 4; j++) {
            const int id = (j & 1) * 256 + tid;  // 0..511 within tile
            const int t  = j >> 1;               // 0:Kf 1:Vf
            const int r  = id >> 3;              // 0..63
            const int c  = id & 7;
            const __half* src = ((t == 0) ? Kf : Vf) + (size_t)(kt + r) * HD_ + c * 8;
            CP16(sb + ATT_Q_B + st * ATT_ST_B + t * 8192 +
                 SWZ128((uint32_t)(r * 128 + c * 16)), src);
        }
        CPCOMMIT();
    };
    load_kv(0, 0);
    load_kv(1, 1);
    load_kv(2, 2);

    CPWAIT(2);             // Q + KV0 ready
    __syncthreads();

    uint32_t qh[4][4], ql[4][4];
    const int arow = wid * 16 + (lane & 15);
    #pragma unroll
    for (int kc = 0; kc < 4; kc++) {
        const uint32_t off = SWZ128((uint32_t)(arow * 128 + (kc * 2 + (lane >> 4)) * 16));
        ldsm_x4(sb + off,         qh[kc][0], qh[kc][1], qh[kc][2], qh[kc][3]);
        ldsm_x4(sb + 16384 + off, ql[kc][0], ql[kc][1], ql[kc][2], ql[kc][3]);
    }

    float o[8][4];
    #pragma unroll
    for (int i = 0; i < 8; i++)
        #pragma unroll
        for (int e = 0; e < 4; e++) o[i][e] = 0.0f;
    float m0r = -1e30f, m1r = -1e30f, l0r = 0.0f, l1r = 0.0f;

    const int krow = (lane & 7) + ((lane >> 4) & 1) * 8;
    const int kchk = (lane >> 3) & 1;
    const int vrow = lane & 15;
    const int vchk = lane >> 4;

    #pragma unroll 1
    for (int it = 0; it < 16; it++) {
        if (it + 3 < 16) load_kv(it + 3, (it + 3) & 3);

        const uint32_t kb = sb + ATT_Q_B + (it & 3) * ATT_ST_B;

        // ---- S = Qh K^T + Ql K^T (2-pass fp16) ---------------------------------
        float s[8][4];
        #pragma unroll
        for (int i = 0; i < 8; i++)
            #pragma unroll
            for (int e = 0; e < 4; e++) s[i][e] = 0.0f;

        #pragma unroll
        for (int kc = 0; kc < 4; kc++) {
            #pragma unroll
            for (int p = 0; p < 4; p++) {
                const uint32_t off =
                    SWZ128((uint32_t)((p * 16 + krow) * 128 + (kc * 2 + kchk) * 16));
                uint32_t h0, h1, h2, h3;
                ldsm_x4(kb + off, h0, h1, h2, h3);
                uint32_t bh0[2] = {h0, h1}, bh1[2] = {h2, h3};
                mma16816h(s[2*p],     qh[kc], bh0);
                mma16816h(s[2*p],     ql[kc], bh0);
                mma16816h(s[2*p + 1], qh[kc], bh1);
                mma16816h(s[2*p + 1], ql[kc], bh1);
            }
        }

        // ---- online softmax ---------------------------------------------------
        float t0 = -1e30f, t1 = -1e30f;
        #pragma unroll
        for (int nt = 0; nt < 8; nt++) {
            t0 = fmaxf(t0, fmaxf(s[nt][0], s[nt][1]));
            t1 = fmaxf(t1, fmaxf(s[nt][2], s[nt][3]));
        }
        t0 = fmaxf(t0, __shfl_xor_sync(0xffffffffu, t0, 1));
        t0 = fmaxf(t0, __shfl_xor_sync(0xffffffffu, t0, 2));
        t1 = fmaxf(t1, __shfl_xor_sync(0xffffffffu, t1, 1));
        t1 = fmaxf(t1, __shfl_xor_sync(0xffffffffu, t1, 2));
        const float mn0 = fmaxf(m0r, t0), mn1 = fmaxf(m1r, t1);
        const float cr0 = ex2f(m0r - mn0), cr1 = ex2f(m1r - mn1);
        m0r = mn0; m1r = mn1;
        l0r *= cr0; l1r *= cr1;
        #pragma unroll
        for (int nt = 0; nt < 8; nt++) {
            o[nt][0] *= cr0; o[nt][1] *= cr0;
            o[nt][2] *= cr1; o[nt][3] *= cr1;
        }
        float ps0 = 0.0f, ps1 = 0.0f;
        #pragma unroll
        for (int nt = 0; nt < 8; nt++) {
            s[nt][0] = ex2f(s[nt][0] - mn0);
            s[nt][1] = ex2f(s[nt][1] - mn0);
            s[nt][2] = ex2f(s[nt][2] - mn1);
            s[nt][3] = ex2f(s[nt][3] - mn1);
            ps0 += s[nt][0] + s[nt][1];
            ps1 += s[nt][2] + s[nt][3];
        }
        l0r += ps0; l1r += ps1;

        // ---- P -> fp16 A-fragments ----------------------------------------------
        uint32_t aph[4][4];
        #pragma unroll
        for (int kc = 0; kc < 4; kc++) {
            #pragma unroll
            for (int g = 0; g < 4; g++) {
                const int nt = 2 * kc + (g >> 1);
                aph[kc][g] = packhf(s[nt][(g & 1) * 2 + 0], s[nt][(g & 1) * 2 + 1]);
            }
        }

        // ---- O += P V (single-pass fp16) ----------------------------------------
        #pragma unroll
        for (int kc = 0; kc < 4; kc++) {
            #pragma unroll
            for (int pr = 0; pr < 4; pr++) {
                const uint32_t off =
                    SWZ128((uint32_t)((kc * 16 + vrow) * 128 + (pr * 2 + vchk) * 16));
                uint32_t h0, h1, h2, h3;
                ldsm_x4t(kb + 8192 + off, h0, h1, h2, h3);
                uint32_t vh0[2] = {h0, h1}, vh1[2] = {h2, h3};
                mma16816h(o[2*pr],     aph[kc], vh0);
                mma16816h(o[2*pr + 1], aph[kc], vh1);
            }
        }

        if (it + 3 < 16)      { CPWAIT(2); }
        else if (it + 2 < 16) { CPWAIT(1); }
        else if (it + 1 < 16) { CPWAIT(0); }
        if (it + 1 < 16) __syncthreads();
    }

    // ---- finalize: write fp16 ctx directly ------------------------------------
    l0r += __shfl_xor_sync(0xffffffffu, l0r, 1);
    l0r += __shfl_xor_sync(0xffffffffu, l0r, 2);
    l1r += __shfl_xor_sync(0xffffffffu, l1r, 1);
    l1r += __shfl_xor_sync(0xffffffffu, l1r, 2);
    const float inv0 = 1.0f / l0r, inv1 = 1.0f / l1r;

    const int b = bh / H_, h = bh - b * H_;
    const int row0 = q0 + wid * 16 + (lane >> 2);
    __half* out0 = g_cf + ((size_t)(b * N_ + row0)) * D_ + h * HD_ + (lane & 3) * 2;
    __half* out1 = out0 + (size_t)8 * D_;
    #pragma unroll
    for (int nt = 0; nt < 8; nt++) {
        *(__half2*)(out0 + nt * 8) = __floats2half2_rn(o[nt][0] * inv0, o[nt][1] * inv0);
        *(__half2*)(out1 + nt * 8) = __floats2half2_rn(o[nt][2] * inv1, o[nt][3] * inv1);
    }
}

// ---------------------------------------------------------------------------
extern "C" void kernel_launch(void* const* d_in, const int* in_sizes, int n_in,
                              void* d_out, int out_size)
{
    const float* x     = (const float*)d_in[0];
    const float* Wqkv  = (const float*)d_in[1];
    const float* bqkv  = (const float*)d_in[2];
    const float* Wproj = (const float*)d_in[3];
    const float* bproj = (const float*)d_in[4];
    float* out = (float*)d_out;

    cudaFuncSetAttribute(mma_gemm<0>, cudaFuncAttributeMaxDynamicSharedMemorySize, SMEM_GEMM);
    cudaFuncSetAttribute(mma_gemm<1>, cudaFuncAttributeMaxDynamicSharedMemorySize, SMEM_GEMM);
    cudaFuncSetAttribute(attn_mma,    cudaFuncAttributeMaxDynamicSharedMemorySize, SMEM_ATTN);

    cvt_x_kernel<<<(M_ * D_ / 4 + 255) / 256, 256>>>(x);
    cvtT_kernel<0><<<dim3(C3_ / 32, D_ / 32), dim3(32, 8)>>>(Wqkv);
    cvtT_kernel<1><<<dim3(D_ / 32, D_ / 32), dim3(32, 8)>>>(Wproj);

    // QKV GEMM (fp16) -> Q split fp16 (pre-scaled), K fp16, V fp16
    mma_gemm<0><<<dim3(C3_ / 128, M_ / 128), 256, SMEM_GEMM>>>(bqkv, nullptr);

    // flash attention: 2-pass fp16 S, fp16 PV -> fp16 ctx
    attn_mma<<<dim3(N_ / 128, B_ * H_), 256, SMEM_ATTN>>>();

    // output projection (fp16)
    mma_gemm<1><<<dim3(D_ / 128, M_ / 128), 256, SMEM_GEMM>>>(bproj, out);
}

// round 9
// speedup vs baseline: 9.5607x; 1.1443x over previous
#include <cuda_runtime.h>
#include <cuda_fp16.h>
#include <cstdint>

#define B_  8
#define N_  1024
#define D_  768
#define H_  12
#define HD_ 64
#define M_  (B_*N_)      // 8192
#define C3_ (3*D_)       // 2304
#define SCLOG2E 0.1803368801111204f   // 0.125 * log2(e)

// ------------------------- scratch (__device__ globals) --------------------
__device__ __half g_cf[(size_t)M_*D_];           // attention output (fp16)

__device__ __half g_qf[(size_t)B_*H_*N_*HD_];    // Q fp16 (pre-scaled)
__device__ __half g_kf[(size_t)B_*H_*N_*HD_];    // K fp16
__device__ __half g_vf[(size_t)B_*H_*N_*HD_];    // V fp16

__device__ __half g_xf[(size_t)M_*D_];           // x   (fp16)
__device__ __half g_wf[(size_t)C3_*D_];          // W_qkv^T  [2304][768] fp16
__device__ __half g_wpf[(size_t)D_*D_];          // W_proj^T [768][768]  fp16

// ------------------------- helpers -----------------------------------------
__device__ __forceinline__ uint32_t smem_u32(const void* p) {
    uint32_t a;
    asm("{ .reg .u64 t; cvta.to.shared.u64 t, %1; cvt.u32.u64 %0, t; }"
        : "=r"(a) : "l"(p));
    return a;
}
#define SWZ64(o)  ((o) ^ (((o) >> 3) & 0x30))
#define SWZ128(o) ((o) ^ (((o) >> 3) & 0x70))

#define CP16(s, g)  asm volatile("cp.async.cg.shared.global [%0], [%1], 16;" :: "r"(s), "l"(g))
#define CPCOMMIT()  asm volatile("cp.async.commit_group;" ::: "memory")
#define CPWAIT(n)   asm volatile("cp.async.wait_group %0;" :: "n"(n) : "memory")

__device__ __forceinline__ void ldsm_x4(uint32_t addr, uint32_t& r0, uint32_t& r1,
                                        uint32_t& r2, uint32_t& r3) {
    asm volatile("ldmatrix.sync.aligned.m8n8.x4.shared.b16 {%0,%1,%2,%3}, [%4];"
                 : "=r"(r0), "=r"(r1), "=r"(r2), "=r"(r3) : "r"(addr));
}
__device__ __forceinline__ void ldsm_x4t(uint32_t addr, uint32_t& r0, uint32_t& r1,
                                         uint32_t& r2, uint32_t& r3) {
    asm volatile("ldmatrix.sync.aligned.m8n8.x4.trans.shared.b16 {%0,%1,%2,%3}, [%4];"
                 : "=r"(r0), "=r"(r1), "=r"(r2), "=r"(r3) : "r"(addr));
}
__device__ __forceinline__ void mma16816h(float* d, const uint32_t* a, const uint32_t* b) {
    asm volatile(
        "mma.sync.aligned.m16n8k16.row.col.f32.f16.f16.f32 "
        "{%0,%1,%2,%3}, {%4,%5,%6,%7}, {%8,%9}, {%0,%1,%2,%3};"
        : "+f"(d[0]), "+f"(d[1]), "+f"(d[2]), "+f"(d[3])
        : "r"(a[0]), "r"(a[1]), "r"(a[2]), "r"(a[3]), "r"(b[0]), "r"(b[1]));
}
__device__ __forceinline__ float ex2f(float x) {
    float y;
    asm("ex2.approx.f32 %0, %1;" : "=f"(y) : "f"(x));
    return y;
}
__device__ __forceinline__ uint32_t packhf(float lo, float hi) {
    uint32_t r;
    asm("cvt.rn.f16x2.f32 %0, %1, %2;" : "=r"(r) : "f"(hi), "f"(lo));
    return r;
}

// ------------------------- conversion kernels ------------------------------
__global__ void cvt_x_kernel(const float* __restrict__ in) {
    int i = blockIdx.x * 256 + threadIdx.x;           // float4 index
    if (i < (M_ * D_) / 4) {
        float4 v = ((const float4*)in)[i];
        ((__half2*)g_xf)[i * 2]     = __floats2half2_rn(v.x, v.y);
        ((__half2*)g_xf)[i * 2 + 1] = __floats2half2_rn(v.z, v.w);
    }
}
template<int WHICH>
__global__ void cvtT_kernel(const float* __restrict__ W) {
    constexpr int K = D_;
    constexpr int N = (WHICH == 0) ? C3_ : D_;
    __half* dst = (WHICH == 0) ? g_wf : g_wpf;
    __shared__ float tile[32][33];
    const int nb = blockIdx.x * 32, kb = blockIdx.y * 32;
    const int tx = threadIdx.x, ty = threadIdx.y;
    #pragma unroll
    for (int r = ty; r < 32; r += 8)
        tile[r][tx] = W[(size_t)(kb + r) * N + nb + tx];
    __syncthreads();
    #pragma unroll
    for (int r = ty; r < 32; r += 8) {
        const int n = nb + r, k = kb + tx;
        dst[(size_t)n * K + k] = __float2half_rn(tile[tx][r]);
    }
}

// ------------------------- fp16 HMMA GEMM, 64x64 warp tiles ------------------
// CTA 128x128, 128 threads (4 warps as 2x2 of 64x64). 4-stage cp.async ring.
#define KSTEP_    32
#define NSTEPS_   (D_ / KSTEP_)    // 24
#define TILE_B    8192             // 128 rows * 64 bytes (fp16 128x32)
#define BUF_B     (2 * TILE_B)     // A, B  (16 KB / stage)
#define NSTAGE_G  4
#define SMEM_GEMM (NSTAGE_G * BUF_B)   // 64 KB

template<int MODE>
__global__ __launch_bounds__(128, 2)
void mma_gemm(const float* __restrict__ bias, float* __restrict__ Cout)
{
    extern __shared__ __align__(1024) char smem[];
    const int tid = threadIdx.x, lane = tid & 31, wid = tid >> 5;
    const int m0 = blockIdx.y * 128, n0 = blockIdx.x * 128;
    const int wm = wid & 1;        // 0..1 -> 64 rows
    const int wn = wid >> 1;       // 0..1 -> 64 cols

    const __half* __restrict__ Af = (MODE == 0) ? g_xf : g_cf;
    const __half* __restrict__ Bf = (MODE == 0) ? g_wf : g_wpf;

    // load mapping: tile = 512 16B-chunks, 128 threads x 4 chunks
    // j-th chunk: row = j*32 + (tid>>2), col chunk = tid&3
    const int lr = tid >> 2, lc = tid & 3;
    uint32_t sAo[4];
    #pragma unroll
    for (int j = 0; j < 4; j++)
        sAo[j] = SWZ64((uint32_t)((j * 32 + lr) * 64 + lc * 16));
    const uint32_t sbase = smem_u32(smem);

    const uint32_t aoff = SWZ64((uint32_t)((wm * 64 + (lane & 15)) * 64 + (lane >> 4) * 16));
    const uint32_t boff = SWZ64((uint32_t)((wn * 64 + (lane & 7) + ((lane & 16) ? 8 : 0)) * 64
                                           + ((lane >> 3) & 1) * 16));

    float acc[4][8][4];
    #pragma unroll
    for (int i = 0; i < 4; i++)
        #pragma unroll
        for (int j = 0; j < 8; j++)
            #pragma unroll
            for (int e = 0; e < 4; e++) acc[i][j][e] = 0.0f;

    auto load_step = [&](int s, int st) {
        const int kt = s * KSTEP_;
        const uint32_t d = sbase + st * BUF_B;
        #pragma unroll
        for (int j = 0; j < 4; j++)
            CP16(d + 0 * TILE_B + sAo[j], Af + (size_t)(m0 + j * 32 + lr) * D_ + kt + lc * 8);
        #pragma unroll
        for (int j = 0; j < 4; j++)
            CP16(d + 1 * TILE_B + sAo[j], Bf + (size_t)(n0 + j * 32 + lr) * D_ + kt + lc * 8);
        CPCOMMIT();
    };

    load_step(0, 0);
    load_step(1, 1);
    load_step(2, 2);
    CPWAIT(2);
    __syncthreads();

    #pragma unroll 1
    for (int s = 0; s < NSTEPS_; s++) {
        if (s + 3 < NSTEPS_) load_step(s + 3, (s + 3) & 3);

        const uint32_t tb = sbase + (s & 3) * BUF_B;
        #pragma unroll
        for (int kk = 0; kk < 2; kk++) {
            const uint32_t kx = kk ? 32u : 0u;
            uint32_t ah[4][4];
            #pragma unroll
            for (int mi = 0; mi < 4; mi++)
                ldsm_x4((tb + 0 * TILE_B + mi * 1024) + (aoff ^ kx),
                        ah[mi][0], ah[mi][1], ah[mi][2], ah[mi][3]);
            uint32_t bh[8][2];
            #pragma unroll
            for (int nb = 0; nb < 4; nb++)
                ldsm_x4((tb + 1 * TILE_B + nb * 1024) + (boff ^ kx),
                        bh[nb*2][0], bh[nb*2][1], bh[nb*2+1][0], bh[nb*2+1][1]);
            #pragma unroll
            for (int mi = 0; mi < 4; mi++)
                #pragma unroll
                for (int ni = 0; ni < 8; ni++)
                    mma16816h(acc[mi][ni], ah[mi], bh[ni]);
        }

        if (s + 3 < NSTEPS_)      { CPWAIT(2); }
        else if (s + 2 < NSTEPS_) { CPWAIT(1); }
        else if (s + 1 < NSTEPS_) { CPWAIT(0); }
        if (s + 1 < NSTEPS_) __syncthreads();
    }

    // ---- epilogue -----------------------------------------------------------
    #pragma unroll
    for (int mi = 0; mi < 4; mi++) {
        #pragma unroll
        for (int ni = 0; ni < 8; ni++) {
            const int cc = n0 + wn * 64 + ni * 8 + (lane & 3) * 2;
            const float b0v = bias[cc], b1v = bias[cc + 1];
            #pragma unroll
            for (int half = 0; half < 2; half++) {
                const int m = m0 + wm * 64 + mi * 16 + (lane >> 2) + half * 8;
                float v0 = acc[mi][ni][half * 2 + 0] + b0v;
                float v1 = acc[mi][ni][half * 2 + 1] + b1v;
                if (MODE == 0) {
                    const int bb = m >> 10, n = m & 1023;
                    const int trip = cc / D_;
                    const int rem = cc - trip * D_;
                    const int h = rem >> 6, d = rem & 63;
                    size_t off = ((((size_t)bb * H_ + h) * N_) + n) * HD_ + d;
                    const float sc = (trip == 0) ? SCLOG2E : 1.0f;
                    __half* dst = (trip == 0) ? g_qf : (trip == 1) ? g_kf : g_vf;
                    *(__half2*)(dst + off) = __floats2half2_rn(v0 * sc, v1 * sc);
                } else {
                    *(float2*)&Cout[(size_t)m * D_ + cc] = make_float2(v0, v1);
                }
            }
        }
    }
}

// ------------------------- HMMA flash attention ------------------------------
// S = Q K^T single-pass fp16 (Q pre-scaled); PV = single-pass fp16.
#define ATT_Q_B   16384                 // Q: 128*128B
#define ATT_ST_B  16384                 // Kf + Vf: 2 * 64*128B
#define NSTAGE_A  4
#define SMEM_ATTN (ATT_Q_B + NSTAGE_A * ATT_ST_B)   // 80 KB

__global__ __launch_bounds__(256, 1)
void attn_mma()
{
    extern __shared__ __align__(1024) char sm[];
    const uint32_t sb = smem_u32(sm);
    const int tid = threadIdx.x, lane = tid & 31, wid = tid >> 5;
    const int bh = blockIdx.y, q0 = blockIdx.x * 128;
    const size_t bo = (size_t)bh * N_ * HD_;

    const __half* __restrict__ Qf = g_qf + bo + (size_t)q0 * HD_;
    const __half* __restrict__ Kf = g_kf + bo;
    const __half* __restrict__ Vf = g_vf + bo;

    // Q tile: 128 rows x 128 B
    #pragma unroll
    for (int j = 0; j < 4; j++) {
        const int id = j * 256 + tid;
        const int r  = id >> 3;
        const int c  = id & 7;
        CP16(sb + SWZ128((uint32_t)(r * 128 + c * 16)), Qf + (size_t)r * HD_ + c * 8);
    }
    CPCOMMIT();

    auto load_kv = [&](int it, int st) {
        const int kt = it * 64;
        #pragma unroll
        for (int j = 0; j < 4; j++) {
            const int id = (j & 1) * 256 + tid;  // 0..511 within tile
            const int t  = j >> 1;               // 0:Kf 1:Vf
            const int r  = id >> 3;              // 0..63
            const int c  = id & 7;
            const __half* src = ((t == 0) ? Kf : Vf) + (size_t)(kt + r) * HD_ + c * 8;
            CP16(sb + ATT_Q_B + st * ATT_ST_B + t * 8192 +
                 SWZ128((uint32_t)(r * 128 + c * 16)), src);
        }
        CPCOMMIT();
    };
    load_kv(0, 0);
    load_kv(1, 1);
    load_kv(2, 2);

    CPWAIT(2);             // Q + KV0 ready
    __syncthreads();

    uint32_t qh[4][4];
    const int arow = wid * 16 + (lane & 15);
    #pragma unroll
    for (int kc = 0; kc < 4; kc++) {
        const uint32_t off = SWZ128((uint32_t)(arow * 128 + (kc * 2 + (lane >> 4)) * 16));
        ldsm_x4(sb + off, qh[kc][0], qh[kc][1], qh[kc][2], qh[kc][3]);
    }

    float o[8][4];
    #pragma unroll
    for (int i = 0; i < 8; i++)
        #pragma unroll
        for (int e = 0; e < 4; e++) o[i][e] = 0.0f;
    float m0r = -1e30f, m1r = -1e30f, l0r = 0.0f, l1r = 0.0f;

    const int krow = (lane & 7) + ((lane >> 4) & 1) * 8;
    const int kchk = (lane >> 3) & 1;
    const int vrow = lane & 15;
    const int vchk = lane >> 4;

    #pragma unroll 1
    for (int it = 0; it < 16; it++) {
        if (it + 3 < 16) load_kv(it + 3, (it + 3) & 3);

        const uint32_t kb = sb + ATT_Q_B + (it & 3) * ATT_ST_B;

        // ---- S = Q K^T (single-pass fp16) --------------------------------------
        float s[8][4];
        #pragma unroll
        for (int i = 0; i < 8; i++)
            #pragma unroll
            for (int e = 0; e < 4; e++) s[i][e] = 0.0f;

        #pragma unroll
        for (int kc = 0; kc < 4; kc++) {
            #pragma unroll
            for (int p = 0; p < 4; p++) {
                const uint32_t off =
                    SWZ128((uint32_t)((p * 16 + krow) * 128 + (kc * 2 + kchk) * 16));
                uint32_t h0, h1, h2, h3;
                ldsm_x4(kb + off, h0, h1, h2, h3);
                uint32_t bh0[2] = {h0, h1}, bh1[2] = {h2, h3};
                mma16816h(s[2*p],     qh[kc], bh0);
                mma16816h(s[2*p + 1], qh[kc], bh1);
            }
        }

        // ---- online softmax ---------------------------------------------------
        float t0 = -1e30f, t1 = -1e30f;
        #pragma unroll
        for (int nt = 0; nt < 8; nt++) {
            t0 = fmaxf(t0, fmaxf(s[nt][0], s[nt][1]));
            t1 = fmaxf(t1, fmaxf(s[nt][2], s[nt][3]));
        }
        t0 = fmaxf(t0, __shfl_xor_sync(0xffffffffu, t0, 1));
        t0 = fmaxf(t0, __shfl_xor_sync(0xffffffffu, t0, 2));
        t1 = fmaxf(t1, __shfl_xor_sync(0xffffffffu, t1, 1));
        t1 = fmaxf(t1, __shfl_xor_sync(0xffffffffu, t1, 2));
        const float mn0 = fmaxf(m0r, t0), mn1 = fmaxf(m1r, t1);
        const float cr0 = ex2f(m0r - mn0), cr1 = ex2f(m1r - mn1);
        m0r = mn0; m1r = mn1;
        l0r *= cr0; l1r *= cr1;
        #pragma unroll
        for (int nt = 0; nt < 8; nt++) {
            o[nt][0] *= cr0; o[nt][1] *= cr0;
            o[nt][2] *= cr1; o[nt][3] *= cr1;
        }
        float ps0 = 0.0f, ps1 = 0.0f;
        #pragma unroll
        for (int nt = 0; nt < 8; nt++) {
            s[nt][0] = ex2f(s[nt][0] - mn0);
            s[nt][1] = ex2f(s[nt][1] - mn0);
            s[nt][2] = ex2f(s[nt][2] - mn1);
            s[nt][3] = ex2f(s[nt][3] - mn1);
            ps0 += s[nt][0] + s[nt][1];
            ps1 += s[nt][2] + s[nt][3];
        }
        l0r += ps0; l1r += ps1;

        // ---- P -> fp16 A-fragments ----------------------------------------------
        uint32_t aph[4][4];
        #pragma unroll
        for (int kc = 0; kc < 4; kc++) {
            #pragma unroll
            for (int g = 0; g < 4; g++) {
                const int nt = 2 * kc + (g >> 1);
                aph[kc][g] = packhf(s[nt][(g & 1) * 2 + 0], s[nt][(g & 1) * 2 + 1]);
            }
        }

        // ---- O += P V (single-pass fp16) ----------------------------------------
        #pragma unroll
        for (int kc = 0; kc < 4; kc++) {
            #pragma unroll
            for (int pr = 0; pr < 4; pr++) {
                const uint32_t off =
                    SWZ128((uint32_t)((kc * 16 + vrow) * 128 + (pr * 2 + vchk) * 16));
                uint32_t h0, h1, h2, h3;
                ldsm_x4t(kb + 8192 + off, h0, h1, h2, h3);
                uint32_t vh0[2] = {h0, h1}, vh1[2] = {h2, h3};
                mma16816h(o[2*pr],     aph[kc], vh0);
                mma16816h(o[2*pr + 1], aph[kc], vh1);
            }
        }

        if (it + 3 < 16)      { CPWAIT(2); }
        else if (it + 2 < 16) { CPWAIT(1); }
        else if (it + 1 < 16) { CPWAIT(0); }
        if (it + 1 < 16) __syncthreads();
    }

    // ---- finalize: write fp16 ctx directly ------------------------------------
    l0r += __shfl_xor_sync(0xffffffffu, l0r, 1);
    l0r += __shfl_xor_sync(0xffffffffu, l0r, 2);
    l1r += __shfl_xor_sync(0xffffffffu, l1r, 1);
    l1r += __shfl_xor_sync(0xffffffffu, l1r, 2);
    const float inv0 = 1.0f / l0r, inv1 = 1.0f / l1r;

    const int b = bh / H_, h = bh - b * H_;
    const int row0 = q0 + wid * 16 + (lane >> 2);
    __half* out0 = g_cf + ((size_t)(b * N_ + row0)) * D_ + h * HD_ + (lane & 3) * 2;
    __half* out1 = out0 + (size_t)8 * D_;
    #pragma unroll
    for (int nt = 0; nt < 8; nt++) {
        *(__half2*)(out0 + nt * 8) = __floats2half2_rn(o[nt][0] * inv0, o[nt][1] * inv0);
        *(__half2*)(out1 + nt * 8) = __floats2half2_rn(o[nt][2] * inv1, o[nt][3] * inv1);
    }
}

// ---------------------------------------------------------------------------
extern "C" void kernel_launch(void* const* d_in, const int* in_sizes, int n_in,
                              void* d_out, int out_size)
{
    const float* x     = (const float*)d_in[0];
    const float* Wqkv  = (const float*)d_in[1];
    const float* bqkv  = (const float*)d_in[2];
    const float* Wproj = (const float*)d_in[3];
    const float* bproj = (const float*)d_in[4];
    float* out = (float*)d_out;

    cudaFuncSetAttribute(mma_gemm<0>, cudaFuncAttributeMaxDynamicSharedMemorySize, SMEM_GEMM);
    cudaFuncSetAttribute(mma_gemm<1>, cudaFuncAttributeMaxDynamicSharedMemorySize, SMEM_GEMM);
    cudaFuncSetAttribute(attn_mma,    cudaFuncAttributeMaxDynamicSharedMemorySize, SMEM_ATTN);

    cvt_x_kernel<<<(M_ * D_ / 4 + 255) / 256, 256>>>(x);
    cvtT_kernel<0><<<dim3(C3_ / 32, D_ / 32), dim3(32, 8)>>>(Wqkv);
    cvtT_kernel<1><<<dim3(D_ / 32, D_ / 32), dim3(32, 8)>>>(Wproj);

    // QKV GEMM (fp16, 64x64 warp tiles) -> Q (pre-scaled), K, V fp16
    mma_gemm<0><<<dim3(C3_ / 128, M_ / 128), 128, SMEM_GEMM>>>(bqkv, nullptr);

    // flash attention: single-pass fp16 S + PV -> fp16 ctx
    attn_mma<<<dim3(N_ / 128, B_ * H_), 256, SMEM_ATTN>>>();

    // output projection (fp16, 64x64 warp tiles)
    mma_gemm<1><<<dim3(D_ / 128, M_ / 128), 128, SMEM_GEMM>>>(bproj, out);
}